// round 5
// baseline (speedup 1.0000x reference)
#include <cuda_runtime.h>
#include <math.h>

// Problem constants (fixed shapes for this dataset)
#define NTOK 16384      // B*T = 4*4096
#define DDIM 1024
#define HDIM 4096
#define NEXP 4

// ---------------- static device scratch (no allocation allowed) ----------------
__device__ int   g_cnt[NEXP];
__device__ int   g_curs[NEXP];
__device__ int   g_offs[NEXP + 1];
__device__ int   g_perm[NTOK];
__device__ float g_Xs[(size_t)NTOK * DDIM];   // 64 MB, expert-sorted input rows
__device__ float g_Hs[(size_t)NTOK * HDIM];   // 256 MB, hidden activations (sorted order)

// ---------------- sorting / gather kernels ----------------
__global__ void k_init() {
    int i = threadIdx.x;
    if (i < NEXP) { g_cnt[i] = 0; g_curs[i] = 0; }
}

__global__ void k_hist(const int* __restrict__ mask) {
    int t = blockIdx.x * blockDim.x + threadIdx.x;
    if (t < NTOK) atomicAdd(&g_cnt[mask[t]], 1);
}

__global__ void k_prefix() {
    if (threadIdx.x == 0) {
        int s = 0;
        for (int i = 0; i < NEXP; i++) { g_offs[i] = s; s += g_cnt[i]; }
        g_offs[NEXP] = s;
    }
}

__global__ void k_scatter(const int* __restrict__ mask) {
    int t = blockIdx.x * blockDim.x + threadIdx.x;
    if (t < NTOK) {
        int m = mask[t];
        int p = g_offs[m] + atomicAdd(&g_curs[m], 1);
        g_perm[p] = t;
    }
}

// one block per sorted row: copy 1024 floats (256 threads * float4)
__global__ void k_gather(const float* __restrict__ x) {
    int row = blockIdx.x;
    int src = g_perm[row];
    const float4* xs = reinterpret_cast<const float4*>(x + (size_t)src * DDIM);
    float4* dst = reinterpret_cast<float4*>(g_Xs + (size_t)row * DDIM);
    dst[threadIdx.x] = xs[threadIdx.x];
}

// ---------------- GEMM stage 1: Hs = gelu(Xs * W1[:NM,:KM]^T + b1) ----------------
// Tile: 128 tokens x 128 hidden, 256 threads, 8x8 per thread, K-step 16.
template <int KM, int NM>
__global__ __launch_bounds__(256, 2)
void k_gemm1(const float* __restrict__ W1, const float* __restrict__ b1, int expert) {
    __shared__ float As[16][128];   // As[k][row]
    __shared__ float Bs[16][128];   // Bs[k][col]

    const int base = g_offs[expert];
    const int cnt  = g_offs[expert + 1] - base;
    const int row0 = blockIdx.x * 128;
    if (row0 >= cnt) return;
    const int col0 = blockIdx.y * 128;

    const int tid = threadIdx.x;
    const int lr = tid >> 2;          // 0..63 : row/col within tile (and +64)
    const int lk = (tid & 3) * 4;     // 0,4,8,12 : k offset (float4)
    const int ty = tid >> 4;          // 0..15
    const int tx = tid & 15;          // 0..15

    const float* Ag = g_Xs + (size_t)(base + row0) * DDIM;  // stride DDIM
    const float* Bg = W1   + (size_t)col0 * DDIM;           // stride DDIM

    float acc[8][8];
#pragma unroll
    for (int i = 0; i < 8; i++)
#pragma unroll
        for (int j = 0; j < 8; j++) acc[i][j] = 0.f;

    for (int k0 = 0; k0 < KM; k0 += 16) {
#pragma unroll
        for (int h = 0; h < 2; h++) {
            int r = lr + h * 64;
            float4 v = make_float4(0.f, 0.f, 0.f, 0.f);
            if (row0 + r < cnt)
                v = *reinterpret_cast<const float4*>(Ag + (size_t)r * DDIM + k0 + lk);
            As[lk + 0][r] = v.x; As[lk + 1][r] = v.y;
            As[lk + 2][r] = v.z; As[lk + 3][r] = v.w;
        }
#pragma unroll
        for (int h = 0; h < 2; h++) {
            int c = lr + h * 64;
            float4 v = *reinterpret_cast<const float4*>(Bg + (size_t)c * DDIM + k0 + lk);
            Bs[lk + 0][c] = v.x; Bs[lk + 1][c] = v.y;
            Bs[lk + 2][c] = v.z; Bs[lk + 3][c] = v.w;
        }
        __syncthreads();

#pragma unroll
        for (int k = 0; k < 16; k++) {
            float4 a0 = *reinterpret_cast<const float4*>(&As[k][ty * 4]);
            float4 a1 = *reinterpret_cast<const float4*>(&As[k][64 + ty * 4]);
            float4 b0 = *reinterpret_cast<const float4*>(&Bs[k][tx * 4]);
            float4 b1v = *reinterpret_cast<const float4*>(&Bs[k][64 + tx * 4]);
            float a[8] = {a0.x, a0.y, a0.z, a0.w, a1.x, a1.y, a1.z, a1.w};
            float b[8] = {b0.x, b0.y, b0.z, b0.w, b1v.x, b1v.y, b1v.z, b1v.w};
#pragma unroll
            for (int i = 0; i < 8; i++)
#pragma unroll
                for (int j = 0; j < 8; j++)
                    acc[i][j] += a[i] * b[j];
        }
        __syncthreads();
    }

#pragma unroll
    for (int i = 0; i < 8; i++) {
        int r = (i < 4) ? (ty * 4 + i) : (64 + ty * 4 + (i - 4));
        if (row0 + r >= cnt) continue;
        float* orow = g_Hs + (size_t)(base + row0 + r) * HDIM + col0;
#pragma unroll
        for (int j = 0; j < 8; j++) {
            int c = (j < 4) ? (tx * 4 + j) : (64 + tx * 4 + (j - 4));
            float h = acc[i][j] + b1[col0 + c];
            orow[c] = 0.5f * h * (1.0f + erff(h * 0.70710678118654752f));  // exact gelu
        }
    }
}

// ---------------- GEMM stage 2: out[perm] = Hs[:, :KM] * W2[:, :KM]^T + b2 ----------------
template <int KM>   // KM = d_hid of this expert
__global__ __launch_bounds__(256, 2)
void k_gemm2(const float* __restrict__ W2, const float* __restrict__ b2,
             float* __restrict__ out, int expert) {
    __shared__ float As[16][128];
    __shared__ float Bs[16][128];

    const int base = g_offs[expert];
    const int cnt  = g_offs[expert + 1] - base;
    const int row0 = blockIdx.x * 128;
    if (row0 >= cnt) return;
    const int col0 = blockIdx.y * 128;   // output dim tile (D=1024 -> 8 tiles)

    const int tid = threadIdx.x;
    const int lr = tid >> 2;
    const int lk = (tid & 3) * 4;
    const int ty = tid >> 4;
    const int tx = tid & 15;

    const float* Ag = g_Hs + (size_t)(base + row0) * HDIM;  // stride HDIM
    const float* Bg = W2   + (size_t)col0 * HDIM;           // stride HDIM

    float acc[8][8];
#pragma unroll
    for (int i = 0; i < 8; i++)
#pragma unroll
        for (int j = 0; j < 8; j++) acc[i][j] = 0.f;

    for (int k0 = 0; k0 < KM; k0 += 16) {
#pragma unroll
        for (int h = 0; h < 2; h++) {
            int r = lr + h * 64;
            float4 v = make_float4(0.f, 0.f, 0.f, 0.f);
            if (row0 + r < cnt)
                v = *reinterpret_cast<const float4*>(Ag + (size_t)r * HDIM + k0 + lk);
            As[lk + 0][r] = v.x; As[lk + 1][r] = v.y;
            As[lk + 2][r] = v.z; As[lk + 3][r] = v.w;
        }
#pragma unroll
        for (int h = 0; h < 2; h++) {
            int c = lr + h * 64;
            float4 v = *reinterpret_cast<const float4*>(Bg + (size_t)c * HDIM + k0 + lk);
            Bs[lk + 0][c] = v.x; Bs[lk + 1][c] = v.y;
            Bs[lk + 2][c] = v.z; Bs[lk + 3][c] = v.w;
        }
        __syncthreads();

#pragma unroll
        for (int k = 0; k < 16; k++) {
            float4 a0 = *reinterpret_cast<const float4*>(&As[k][ty * 4]);
            float4 a1 = *reinterpret_cast<const float4*>(&As[k][64 + ty * 4]);
            float4 b0 = *reinterpret_cast<const float4*>(&Bs[k][tx * 4]);
            float4 b1v = *reinterpret_cast<const float4*>(&Bs[k][64 + tx * 4]);
            float a[8] = {a0.x, a0.y, a0.z, a0.w, a1.x, a1.y, a1.z, a1.w};
            float b[8] = {b0.x, b0.y, b0.z, b0.w, b1v.x, b1v.y, b1v.z, b1v.w};
#pragma unroll
            for (int i = 0; i < 8; i++)
#pragma unroll
                for (int j = 0; j < 8; j++)
                    acc[i][j] += a[i] * b[j];
        }
        __syncthreads();
    }

#pragma unroll
    for (int i = 0; i < 8; i++) {
        int r = (i < 4) ? (ty * 4 + i) : (64 + ty * 4 + (i - 4));
        if (row0 + r >= cnt) continue;
        int token = g_perm[base + row0 + r];
        float* orow = out + (size_t)token * DDIM + col0;
#pragma unroll
        for (int j = 0; j < 8; j++) {
            int c = (j < 4) ? (tx * 4 + j) : (64 + tx * 4 + (j - 4));
            orow[c] = acc[i][j] + b2[col0 + c];
        }
    }
}

// ---------------- launch ----------------
extern "C" void kernel_launch(void* const* d_in, const int* in_sizes, int n_in,
                              void* d_out, int out_size) {
    const float* x    = (const float*)d_in[0];
    const int*   mask = (const int*)d_in[1];
    const float* W1   = (const float*)d_in[2];
    const float* b1   = (const float*)d_in[3];
    const float* W2   = (const float*)d_in[4];
    const float* b2   = (const float*)d_in[5];
    float* out = (float*)d_out;

    k_init<<<1, 32>>>();
    k_hist<<<NTOK / 256, 256>>>(mask);
    k_prefix<<<1, 32>>>();
    k_scatter<<<NTOK / 256, 256>>>(mask);
    k_gather<<<NTOK, 256>>>(x);

    dim3 blk(256);
    // Stage 1: per-expert expand+gelu. Row tiles over-launched (counts are device-side).
    k_gemm1< 128,  512><<<dim3(128,  4), blk>>>(W1, b1, 0);
    k_gemm1< 256, 1024><<<dim3(128,  8), blk>>>(W1, b1, 1);
    k_gemm1< 512, 2048><<<dim3(128, 16), blk>>>(W1, b1, 2);
    k_gemm1<1024, 4096><<<dim3(128, 32), blk>>>(W1, b1, 3);
    // Stage 2: per-expert contract + scatter to original token order.
    k_gemm2< 512><<<dim3(128, 8), blk>>>(W2, b2, out, 0);
    k_gemm2<1024><<<dim3(128, 8), blk>>>(W2, b2, out, 1);
    k_gemm2<2048><<<dim3(128, 8), blk>>>(W2, b2, out, 2);
    k_gemm2<4096><<<dim3(128, 8), blk>>>(W2, b2, out, 3);
}

// round 6
// speedup vs baseline: 1.0506x; 1.0506x over previous
#include <cuda_runtime.h>
#include <math.h>

// Problem constants (fixed shapes for this dataset)
#define NTOK 16384      // B*T = 4*4096
#define DDIM 1024
#define HDIM 4096
#define NEXP 4

typedef unsigned long long u64;

// ---------------- packed f32x2 helpers (Blackwell sm_103a) ----------------
__device__ __forceinline__ void ffma2(u64 &d, u64 a, u64 b) {
    asm("fma.rn.f32x2 %0, %1, %2, %0;" : "+l"(d) : "l"(a), "l"(b));
}
__device__ __forceinline__ u64 pack2dup(float a) {
    u64 r; asm("mov.b64 %0, {%1, %1};" : "=l"(r) : "f"(a)); return r;
}
__device__ __forceinline__ void unpack2(u64 v, float &lo, float &hi) {
    asm("mov.b64 {%0, %1}, %2;" : "=f"(lo), "=f"(hi) : "l"(v));
}

// ---------------- static device scratch (no allocation allowed) ----------------
__device__ int   g_cnt[NEXP];
__device__ int   g_curs[NEXP];
__device__ int   g_offs[NEXP + 1];
__device__ int   g_perm[NTOK];
__device__ float g_Xs[(size_t)NTOK * DDIM];   // 64 MB, expert-sorted input rows
__device__ float g_Hs[(size_t)NTOK * HDIM];   // 256 MB, hidden activations (sorted order)

// ---------------- sorting / gather kernels ----------------
__global__ void k_init() {
    int i = threadIdx.x;
    if (i < NEXP) { g_cnt[i] = 0; g_curs[i] = 0; }
}

__global__ void k_hist(const int* __restrict__ mask) {
    int t = blockIdx.x * blockDim.x + threadIdx.x;
    if (t < NTOK) atomicAdd(&g_cnt[mask[t]], 1);
}

__global__ void k_prefix() {
    if (threadIdx.x == 0) {
        int s = 0;
        for (int i = 0; i < NEXP; i++) { g_offs[i] = s; s += g_cnt[i]; }
        g_offs[NEXP] = s;
    }
}

__global__ void k_scatter(const int* __restrict__ mask) {
    int t = blockIdx.x * blockDim.x + threadIdx.x;
    if (t < NTOK) {
        int m = mask[t];
        int p = g_offs[m] + atomicAdd(&g_curs[m], 1);
        g_perm[p] = t;
    }
}

// one block per sorted row: copy 1024 floats (256 threads * float4)
__global__ void k_gather(const float* __restrict__ x) {
    int row = blockIdx.x;
    int src = g_perm[row];
    const float4* xs = reinterpret_cast<const float4*>(x + (size_t)src * DDIM);
    float4* dst = reinterpret_cast<float4*>(g_Xs + (size_t)row * DDIM);
    dst[threadIdx.x] = xs[threadIdx.x];
}

// ---------------- GEMM stage 1: Hs = gelu(Xs * W1[:NM,:KM]^T + b1) ----------------
// Tile: 128 tokens x 128 hidden, 256 threads, 8x8 per thread (packed 8x4 f32x2), K-step 16.
template <int KM, int NM>
__global__ __launch_bounds__(256, 2)
void k_gemm1(const float* __restrict__ W1, const float* __restrict__ b1, int expert) {
    __shared__ float As[16][128];   // As[k][row]
    __shared__ float Bs[16][128];   // Bs[k][col]

    const int base = g_offs[expert];
    const int cnt  = g_offs[expert + 1] - base;
    const int row0 = blockIdx.x * 128;
    if (row0 >= cnt) return;
    const int col0 = blockIdx.y * 128;

    const int tid = threadIdx.x;
    const int lr = tid >> 2;          // 0..63 : row/col within tile (and +64)
    const int lk = (tid & 3) * 4;     // 0,4,8,12 : k offset (float4)
    const int ty = tid >> 4;          // 0..15
    const int tx = tid & 15;          // 0..15

    const float* Ag = g_Xs + (size_t)(base + row0) * DDIM;  // stride DDIM
    const float* Bg = W1   + (size_t)col0 * DDIM;           // stride DDIM

    u64 acc[8][4];
#pragma unroll
    for (int i = 0; i < 8; i++)
#pragma unroll
        for (int j = 0; j < 4; j++) acc[i][j] = 0ull;

    for (int k0 = 0; k0 < KM; k0 += 16) {
#pragma unroll
        for (int h = 0; h < 2; h++) {
            int r = lr + h * 64;
            float4 v = make_float4(0.f, 0.f, 0.f, 0.f);
            if (row0 + r < cnt)
                v = *reinterpret_cast<const float4*>(Ag + (size_t)r * DDIM + k0 + lk);
            As[lk + 0][r] = v.x; As[lk + 1][r] = v.y;
            As[lk + 2][r] = v.z; As[lk + 3][r] = v.w;
        }
#pragma unroll
        for (int h = 0; h < 2; h++) {
            int c = lr + h * 64;
            float4 v = *reinterpret_cast<const float4*>(Bg + (size_t)c * DDIM + k0 + lk);
            Bs[lk + 0][c] = v.x; Bs[lk + 1][c] = v.y;
            Bs[lk + 2][c] = v.z; Bs[lk + 3][c] = v.w;
        }
        __syncthreads();

#pragma unroll
        for (int k = 0; k < 16; k++) {
            float4 a0 = *reinterpret_cast<const float4*>(&As[k][ty * 4]);
            float4 a1 = *reinterpret_cast<const float4*>(&As[k][64 + ty * 4]);
            // LDS.128 lands pairs (x,y)/(z,w) in aligned reg pairs: free packed operands
            ulonglong2 bq0 = *reinterpret_cast<const ulonglong2*>(&Bs[k][tx * 4]);
            ulonglong2 bq1 = *reinterpret_cast<const ulonglong2*>(&Bs[k][64 + tx * 4]);
            u64 bp[4] = {bq0.x, bq0.y, bq1.x, bq1.y};
            float av[8] = {a0.x, a0.y, a0.z, a0.w, a1.x, a1.y, a1.z, a1.w};
#pragma unroll
            for (int i = 0; i < 8; i++) {
                u64 ap = pack2dup(av[i]);
#pragma unroll
                for (int j = 0; j < 4; j++)
                    ffma2(acc[i][j], ap, bp[j]);
            }
        }
        __syncthreads();
    }

#pragma unroll
    for (int i = 0; i < 8; i++) {
        int r = (i < 4) ? (ty * 4 + i) : (64 + ty * 4 + (i - 4));
        if (row0 + r >= cnt) continue;
        float* orow = g_Hs + (size_t)(base + row0 + r) * HDIM + col0;
#pragma unroll
        for (int p = 0; p < 4; p++) {
            int c = (p < 2) ? (tx * 4 + 2 * p) : (64 + tx * 4 + 2 * (p - 2));
            float v0, v1;
            unpack2(acc[i][p], v0, v1);
            float h0 = v0 + b1[col0 + c];
            float h1 = v1 + b1[col0 + c + 1];
            orow[c]     = 0.5f * h0 * (1.0f + erff(h0 * 0.70710678118654752f));
            orow[c + 1] = 0.5f * h1 * (1.0f + erff(h1 * 0.70710678118654752f));
        }
    }
}

// ---------------- GEMM stage 2: out[perm] = Hs[:, :KM] * W2[:, :KM]^T + b2 ----------------
template <int KM>   // KM = d_hid of this expert
__global__ __launch_bounds__(256, 2)
void k_gemm2(const float* __restrict__ W2, const float* __restrict__ b2,
             float* __restrict__ out, int expert) {
    __shared__ float As[16][128];
    __shared__ float Bs[16][128];

    const int base = g_offs[expert];
    const int cnt  = g_offs[expert + 1] - base;
    const int row0 = blockIdx.x * 128;
    if (row0 >= cnt) return;
    const int col0 = blockIdx.y * 128;   // output dim tile (D=1024 -> 8 tiles)

    const int tid = threadIdx.x;
    const int lr = tid >> 2;
    const int lk = (tid & 3) * 4;
    const int ty = tid >> 4;
    const int tx = tid & 15;

    const float* Ag = g_Hs + (size_t)(base + row0) * HDIM;  // stride HDIM
    const float* Bg = W2   + (size_t)col0 * HDIM;           // stride HDIM

    u64 acc[8][4];
#pragma unroll
    for (int i = 0; i < 8; i++)
#pragma unroll
        for (int j = 0; j < 4; j++) acc[i][j] = 0ull;

    for (int k0 = 0; k0 < KM; k0 += 16) {
#pragma unroll
        for (int h = 0; h < 2; h++) {
            int r = lr + h * 64;
            float4 v = make_float4(0.f, 0.f, 0.f, 0.f);
            if (row0 + r < cnt)
                v = *reinterpret_cast<const float4*>(Ag + (size_t)r * HDIM + k0 + lk);
            As[lk + 0][r] = v.x; As[lk + 1][r] = v.y;
            As[lk + 2][r] = v.z; As[lk + 3][r] = v.w;
        }
#pragma unroll
        for (int h = 0; h < 2; h++) {
            int c = lr + h * 64;
            float4 v = *reinterpret_cast<const float4*>(Bg + (size_t)c * HDIM + k0 + lk);
            Bs[lk + 0][c] = v.x; Bs[lk + 1][c] = v.y;
            Bs[lk + 2][c] = v.z; Bs[lk + 3][c] = v.w;
        }
        __syncthreads();

#pragma unroll
        for (int k = 0; k < 16; k++) {
            float4 a0 = *reinterpret_cast<const float4*>(&As[k][ty * 4]);
            float4 a1 = *reinterpret_cast<const float4*>(&As[k][64 + ty * 4]);
            ulonglong2 bq0 = *reinterpret_cast<const ulonglong2*>(&Bs[k][tx * 4]);
            ulonglong2 bq1 = *reinterpret_cast<const ulonglong2*>(&Bs[k][64 + tx * 4]);
            u64 bp[4] = {bq0.x, bq0.y, bq1.x, bq1.y};
            float av[8] = {a0.x, a0.y, a0.z, a0.w, a1.x, a1.y, a1.z, a1.w};
#pragma unroll
            for (int i = 0; i < 8; i++) {
                u64 ap = pack2dup(av[i]);
#pragma unroll
                for (int j = 0; j < 4; j++)
                    ffma2(acc[i][j], ap, bp[j]);
            }
        }
        __syncthreads();
    }

#pragma unroll
    for (int i = 0; i < 8; i++) {
        int r = (i < 4) ? (ty * 4 + i) : (64 + ty * 4 + (i - 4));
        if (row0 + r >= cnt) continue;
        int token = g_perm[base + row0 + r];
        float* orow = out + (size_t)token * DDIM + col0;
#pragma unroll
        for (int p = 0; p < 4; p++) {
            int c = (p < 2) ? (tx * 4 + 2 * p) : (64 + tx * 4 + 2 * (p - 2));
            float v0, v1;
            unpack2(acc[i][p], v0, v1);
            orow[c]     = v0 + b2[col0 + c];
            orow[c + 1] = v1 + b2[col0 + c + 1];
        }
    }
}

// ---------------- launch ----------------
extern "C" void kernel_launch(void* const* d_in, const int* in_sizes, int n_in,
                              void* d_out, int out_size) {
    const float* x    = (const float*)d_in[0];
    const int*   mask = (const int*)d_in[1];
    const float* W1   = (const float*)d_in[2];
    const float* b1   = (const float*)d_in[3];
    const float* W2   = (const float*)d_in[4];
    const float* b2   = (const float*)d_in[5];
    float* out = (float*)d_out;

    k_init<<<1, 32>>>();
    k_hist<<<NTOK / 256, 256>>>(mask);
    k_prefix<<<1, 32>>>();
    k_scatter<<<NTOK / 256, 256>>>(mask);
    k_gather<<<NTOK, 256>>>(x);

    dim3 blk(256);
    // Stage 1: per-expert expand+gelu. Row tiles over-launched (counts are device-side).
    k_gemm1< 128,  512><<<dim3(128,  4), blk>>>(W1, b1, 0);
    k_gemm1< 256, 1024><<<dim3(128,  8), blk>>>(W1, b1, 1);
    k_gemm1< 512, 2048><<<dim3(128, 16), blk>>>(W1, b1, 2);
    k_gemm1<1024, 4096><<<dim3(128, 32), blk>>>(W1, b1, 3);
    // Stage 2: per-expert contract + scatter to original token order.
    k_gemm2< 512><<<dim3(128, 8), blk>>>(W2, b2, out, 0);
    k_gemm2<1024><<<dim3(128, 8), blk>>>(W2, b2, out, 1);
    k_gemm2<2048><<<dim3(128, 8), blk>>>(W2, b2, out, 2);
    k_gemm2<4096><<<dim3(128, 8), blk>>>(W2, b2, out, 3);
}

// round 7
// speedup vs baseline: 2.1946x; 2.0889x over previous
#include <cuda_runtime.h>
#include <cuda_bf16.h>
#include <math.h>

// Problem constants (fixed shapes for this dataset)
#define NTOK 16384      // B*T
#define DDIM 1024
#define HDIM 4096
#define NEXP 4

#define PITCH 40                 // smem row pitch in bf16 (80B: conflict-free ldmatrix)
#define TILE_ELEMS (128 * PITCH) // per tile buffer
#define SMEM_BYTES (2 * 4 * TILE_ELEMS * 2)  // 2 bufs x 4 tiles (Ah,Al,Bh,Bl) = 81920B

// ---------------- static device scratch (no allocation allowed) ----------------
__device__ int g_cnt[NEXP], g_curs[NEXP], g_offs[NEXP + 1], g_perm[NTOK];
__device__ __nv_bfloat16 g_Xh[(size_t)NTOK * DDIM], g_Xl[(size_t)NTOK * DDIM];   // 32MB each
__device__ __nv_bfloat16 g_W1h[(size_t)HDIM * DDIM], g_W1l[(size_t)HDIM * DDIM]; // 8MB each
__device__ __nv_bfloat16 g_W2h[(size_t)DDIM * HDIM], g_W2l[(size_t)DDIM * HDIM]; // 8MB each
__device__ __nv_bfloat16 g_Hh[(size_t)NTOK * HDIM], g_Hl[(size_t)NTOK * HDIM];   // 128MB each

// ---------------- PTX helpers ----------------
__device__ __forceinline__ void ldm4(unsigned r[4], unsigned addr) {
    asm volatile("ldmatrix.sync.aligned.m8n8.x4.shared.b16 {%0,%1,%2,%3}, [%4];"
                 : "=r"(r[0]), "=r"(r[1]), "=r"(r[2]), "=r"(r[3]) : "r"(addr));
}
__device__ __forceinline__ void mma16816(float d[4], const unsigned a[4], unsigned b0, unsigned b1) {
    asm volatile("mma.sync.aligned.m16n8k16.row.col.f32.bf16.bf16.f32 "
                 "{%0,%1,%2,%3}, {%4,%5,%6,%7}, {%8,%9}, {%0,%1,%2,%3};"
                 : "+f"(d[0]), "+f"(d[1]), "+f"(d[2]), "+f"(d[3])
                 : "r"(a[0]), "r"(a[1]), "r"(a[2]), "r"(a[3]), "r"(b0), "r"(b1));
}
__device__ __forceinline__ void cpa16(unsigned dst, const void* src, bool valid) {
    int sz = valid ? 16 : 0;
    asm volatile("cp.async.cg.shared.global [%0], [%1], 16, %2;" :: "r"(dst), "l"(src), "r"(sz));
}
__device__ __forceinline__ float gelu_exact(float v) {
    return 0.5f * v * (1.0f + erff(v * 0.70710678118654752f));
}

// ---------------- sorting / split / gather kernels ----------------
__global__ void k_init() {
    int i = threadIdx.x;
    if (i < NEXP) { g_cnt[i] = 0; g_curs[i] = 0; }
}
__global__ void k_hist(const int* __restrict__ mask) {
    int t = blockIdx.x * blockDim.x + threadIdx.x;
    if (t < NTOK) atomicAdd(&g_cnt[mask[t]], 1);
}
__global__ void k_prefix() {
    if (threadIdx.x == 0) {
        int s = 0;
        for (int i = 0; i < NEXP; i++) { g_offs[i] = s; s += g_cnt[i]; }
        g_offs[NEXP] = s;
    }
}
__global__ void k_scatter(const int* __restrict__ mask) {
    int t = blockIdx.x * blockDim.x + threadIdx.x;
    if (t < NTOK) {
        int m = mask[t];
        int p = g_offs[m] + atomicAdd(&g_curs[m], 1);
        g_perm[p] = t;
    }
}

// split fp32 weight matrix into bf16 hi + bf16 lo(residual). sel: 0=W1, 1=W2
__global__ void k_splitW(const float* __restrict__ W, int sel, int n4) {
    int i = blockIdx.x * blockDim.x + threadIdx.x;
    if (i >= n4) return;
    __nv_bfloat16* Wh = sel ? g_W2h : g_W1h;
    __nv_bfloat16* Wl = sel ? g_W2l : g_W1l;
    float4 v = reinterpret_cast<const float4*>(W)[i];
    float vv[4] = {v.x, v.y, v.z, v.w};
    __nv_bfloat16 h[4], l[4];
#pragma unroll
    for (int j = 0; j < 4; j++) {
        h[j] = __float2bfloat16(vv[j]);
        l[j] = __float2bfloat16(vv[j] - __bfloat162float(h[j]));
    }
    reinterpret_cast<__nv_bfloat162*>(Wh)[i * 2 + 0] = __halves2bfloat162(h[0], h[1]);
    reinterpret_cast<__nv_bfloat162*>(Wh)[i * 2 + 1] = __halves2bfloat162(h[2], h[3]);
    reinterpret_cast<__nv_bfloat162*>(Wl)[i * 2 + 0] = __halves2bfloat162(l[0], l[1]);
    reinterpret_cast<__nv_bfloat162*>(Wl)[i * 2 + 1] = __halves2bfloat162(l[2], l[3]);
}

// gather sorted rows of x and split to bf16 hi/lo. one block per row, 256 thr x float4.
__global__ void k_gather(const float* __restrict__ x) {
    int row = blockIdx.x;
    int src = g_perm[row];
    int t = threadIdx.x;
    float4 v = reinterpret_cast<const float4*>(x + (size_t)src * DDIM)[t];
    float vv[4] = {v.x, v.y, v.z, v.w};
    __nv_bfloat16 h[4], l[4];
#pragma unroll
    for (int j = 0; j < 4; j++) {
        h[j] = __float2bfloat16(vv[j]);
        l[j] = __float2bfloat16(vv[j] - __bfloat162float(h[j]));
    }
    __nv_bfloat162* ph = reinterpret_cast<__nv_bfloat162*>(g_Xh + (size_t)row * DDIM);
    __nv_bfloat162* pl = reinterpret_cast<__nv_bfloat162*>(g_Xl + (size_t)row * DDIM);
    ph[t * 2 + 0] = __halves2bfloat162(h[0], h[1]);
    ph[t * 2 + 1] = __halves2bfloat162(h[2], h[3]);
    pl[t * 2 + 0] = __halves2bfloat162(l[0], l[1]);
    pl[t * 2 + 1] = __halves2bfloat162(l[2], l[3]);
}

// ---------------- tensor-core GEMM (3-term bf16 split, fp32 accum) ----------------
// CTA tile 128(M) x 128(N), K-step 32, 8 warps (4M x 2N), warp tile 32x64.
// S1: A = Xs (LD=DDIM), B = W1 (LD=DDIM), epilogue gelu -> Hh/Hl (bf16 split).
// !S1: A = Hs (LD=HDIM), B = W2 (LD=HDIM), epilogue bias -> out[perm] fp32.
template <int KM, bool S1>
__global__ __launch_bounds__(256)
void k_mm(const float* __restrict__ bias, float* __restrict__ out, int expert) {
    const int base = g_offs[expert];
    const int cnt  = g_offs[expert + 1] - base;
    const int row0 = blockIdx.x * 128;
    if (row0 >= cnt) return;
    const int col0 = blockIdx.y * 128;

    extern __shared__ __nv_bfloat16 sm[];
    const unsigned sbase = (unsigned)__cvta_generic_to_shared(sm);

    const __nv_bfloat16* Aph = S1 ? g_Xh : g_Hh;
    const __nv_bfloat16* Apl = S1 ? g_Xl : g_Hl;
    const __nv_bfloat16* Bph = S1 ? g_W1h : g_W2h;
    const __nv_bfloat16* Bpl = S1 ? g_W1l : g_W2l;
    const int LD = S1 ? DDIM : HDIM;

    const int tid  = threadIdx.x;
    const int lane = tid & 31;
    const int wrp  = tid >> 5;
    const int wm   = wrp & 3;   // M quad: rows wm*32
    const int wn   = wrp >> 2;  // N half: cols wn*64

    // cp.async chunk coords: thread covers chunks {tid, tid+256}; chunk c -> row c>>2, pos c&3 (16B units)
    const int crow = tid >> 2;
    const int cpos = tid & 3;

    // ldmatrix lane offsets
    const int a_r  = lane & 15;
    const int a_c8 = (lane >> 4) << 3;
    const int b_n  = (lane & 7) | ((lane >> 4) << 3);
    const int b_k8 = lane & 8;

    float acc[16][4];
#pragma unroll
    for (int i = 0; i < 16; i++)
#pragma unroll
        for (int j = 0; j < 4; j++) acc[i][j] = 0.f;

    auto issue = [&](int buf, int k0) {
        unsigned sb = sbase + buf * 4 * TILE_ELEMS * 2;
#pragma unroll
        for (int h = 0; h < 2; h++) {
            int row = crow + h * 64;
            unsigned soff = (unsigned)(row * PITCH + cpos * 8) * 2;
            // A rows (guard against cnt)
            bool v = (row0 + row) < cnt;
            int ar = base + (v ? (row0 + row) : 0);
            size_t ao = (size_t)ar * LD + k0 + cpos * 8;
            cpa16(sb + 0 * TILE_ELEMS * 2 + soff, Aph + ao, v);
            cpa16(sb + 1 * TILE_ELEMS * 2 + soff, Apl + ao, v);
            // B rows (always valid: grid.y bounded by NM)
            size_t bo = (size_t)(col0 + row) * LD + k0 + cpos * 8;
            cpa16(sb + 2 * TILE_ELEMS * 2 + soff, Bph + bo, true);
            cpa16(sb + 3 * TILE_ELEMS * 2 + soff, Bpl + bo, true);
        }
    };

    const int nK = KM / 32;
    issue(0, 0);
    asm volatile("cp.async.commit_group;");

    int buf = 0;
    for (int ki = 0; ki < nK; ki++) {
        if (ki + 1 < nK) issue(buf ^ 1, (ki + 1) * 32);
        asm volatile("cp.async.commit_group;");
        if (ki + 1 < nK) asm volatile("cp.async.wait_group 1;");
        else             asm volatile("cp.async.wait_group 0;");
        __syncthreads();

        unsigned sb  = sbase + buf * 4 * TILE_ELEMS * 2;
        unsigned sAh = sb;
        unsigned sAl = sb + 1 * TILE_ELEMS * 2;
        unsigned sBh = sb + 2 * TILE_ELEMS * 2;
        unsigned sBl = sb + 3 * TILE_ELEMS * 2;

#pragma unroll
        for (int kk = 0; kk < 32; kk += 16) {
            unsigned ah[2][4], al[2][4];
#pragma unroll
            for (int mi = 0; mi < 2; mi++) {
                unsigned off = (unsigned)((wm * 32 + mi * 16 + a_r) * PITCH + kk + a_c8) * 2;
                ldm4(ah[mi], sAh + off);
                ldm4(al[mi], sAl + off);
            }
#pragma unroll
            for (int jp = 0; jp < 4; jp++) {
                unsigned bh[4], bl[4];
                unsigned off = (unsigned)((wn * 64 + jp * 16 + b_n) * PITCH + kk + b_k8) * 2;
                ldm4(bh, sBh + off);
                ldm4(bl, sBl + off);
#pragma unroll
                for (int mi = 0; mi < 2; mi++) {
#pragma unroll
                    for (int s = 0; s < 2; s++) {
                        float* d = acc[mi * 8 + jp * 2 + s];
                        mma16816(d, ah[mi], bh[2 * s], bh[2 * s + 1]);   // hi*hi
                        mma16816(d, ah[mi], bl[2 * s], bl[2 * s + 1]);   // hi*lo
                        mma16816(d, al[mi], bh[2 * s], bh[2 * s + 1]);   // lo*hi
                    }
                }
            }
        }
        __syncthreads();
        buf ^= 1;
    }

    // ---------------- epilogue ----------------
    const int er = lane >> 2;
    const int ec = (lane & 3) * 2;
#pragma unroll
    for (int mi = 0; mi < 2; mi++) {
#pragma unroll
        for (int nj = 0; nj < 8; nj++) {
            const float* d = acc[mi * 8 + nj];
            int c = col0 + wn * 64 + nj * 8 + ec;
            float ba = bias[c], bb = bias[c + 1];
#pragma unroll
            for (int half = 0; half < 2; half++) {
                int r = row0 + wm * 32 + mi * 16 + er + half * 8;
                if (r >= cnt) continue;
                float v0 = d[half * 2 + 0] + ba;
                float v1 = d[half * 2 + 1] + bb;
                if (S1) {
                    v0 = gelu_exact(v0);
                    v1 = gelu_exact(v1);
                    __nv_bfloat16 h0 = __float2bfloat16(v0);
                    __nv_bfloat16 h1 = __float2bfloat16(v1);
                    __nv_bfloat16 l0 = __float2bfloat16(v0 - __bfloat162float(h0));
                    __nv_bfloat16 l1 = __float2bfloat16(v1 - __bfloat162float(h1));
                    size_t o = (size_t)(base + r) * HDIM + c;
                    *reinterpret_cast<__nv_bfloat162*>(g_Hh + o) = __halves2bfloat162(h0, h1);
                    *reinterpret_cast<__nv_bfloat162*>(g_Hl + o) = __halves2bfloat162(l0, l1);
                } else {
                    int tok = g_perm[base + r];
                    float2 o2 = make_float2(v0, v1);
                    *reinterpret_cast<float2*>(out + (size_t)tok * DDIM + c) = o2;
                }
            }
        }
    }
}

// ---------------- launch ----------------
extern "C" void kernel_launch(void* const* d_in, const int* in_sizes, int n_in,
                              void* d_out, int out_size) {
    const float* x    = (const float*)d_in[0];
    const int*   mask = (const int*)d_in[1];
    const float* W1   = (const float*)d_in[2];
    const float* b1   = (const float*)d_in[3];
    const float* W2   = (const float*)d_in[4];
    const float* b2   = (const float*)d_in[5];
    float* out = (float*)d_out;

    // opt in to 80KB dynamic smem (host-side config, not a stream op)
    cudaFuncSetAttribute(k_mm< 128, true >, cudaFuncAttributeMaxDynamicSharedMemorySize, SMEM_BYTES);
    cudaFuncSetAttribute(k_mm< 256, true >, cudaFuncAttributeMaxDynamicSharedMemorySize, SMEM_BYTES);
    cudaFuncSetAttribute(k_mm< 512, true >, cudaFuncAttributeMaxDynamicSharedMemorySize, SMEM_BYTES);
    cudaFuncSetAttribute(k_mm<1024, true >, cudaFuncAttributeMaxDynamicSharedMemorySize, SMEM_BYTES);
    cudaFuncSetAttribute(k_mm< 512, false>, cudaFuncAttributeMaxDynamicSharedMemorySize, SMEM_BYTES);
    cudaFuncSetAttribute(k_mm<1024, false>, cudaFuncAttributeMaxDynamicSharedMemorySize, SMEM_BYTES);
    cudaFuncSetAttribute(k_mm<2048, false>, cudaFuncAttributeMaxDynamicSharedMemorySize, SMEM_BYTES);
    cudaFuncSetAttribute(k_mm<4096, false>, cudaFuncAttributeMaxDynamicSharedMemorySize, SMEM_BYTES);

    k_init<<<1, 32>>>();
    k_hist<<<NTOK / 256, 256>>>(mask);
    k_prefix<<<1, 32>>>();
    k_scatter<<<NTOK / 256, 256>>>(mask);
    k_splitW<<<(HDIM * DDIM / 4) / 256, 256>>>(W1, 0, HDIM * DDIM / 4);
    k_splitW<<<(DDIM * HDIM / 4) / 256, 256>>>(W2, 1, DDIM * HDIM / 4);
    k_gather<<<NTOK, 256>>>(x);

    // Stage 1: per-expert expand + gelu (row tiles over-launched; device-side early exit)
    k_mm< 128, true ><<<dim3(128,  4), 256, SMEM_BYTES>>>(b1, nullptr, 0);
    k_mm< 256, true ><<<dim3(128,  8), 256, SMEM_BYTES>>>(b1, nullptr, 1);
    k_mm< 512, true ><<<dim3(128, 16), 256, SMEM_BYTES>>>(b1, nullptr, 2);
    k_mm<1024, true ><<<dim3(128, 32), 256, SMEM_BYTES>>>(b1, nullptr, 3);
    // Stage 2: per-expert contract + scatter to original token order
    k_mm< 512, false><<<dim3(128, 8), 256, SMEM_BYTES>>>(b2, out, 0);
    k_mm<1024, false><<<dim3(128, 8), 256, SMEM_BYTES>>>(b2, out, 1);
    k_mm<2048, false><<<dim3(128, 8), 256, SMEM_BYTES>>>(b2, out, 2);
    k_mm<4096, false><<<dim3(128, 8), 256, SMEM_BYTES>>>(b2, out, 3);
}

// round 9
// speedup vs baseline: 2.2528x; 1.0265x over previous
#include <cuda_runtime.h>
#include <cuda_bf16.h>
#include <math.h>
#include <stdint.h>

// Problem constants (fixed shapes for this dataset)
#define NTOK 16384      // B*T
#define DDIM 1024
#define HDIM 4096
#define NEXP 4

#define PITCH 40                  // smem row pitch in bf16 (80B)
// Per-buffer tile layout (elems): Ah[128*40], Al[128*40], Bh[256*40], Bl[256*40]
#define AH_OFF 0
#define AL_OFF (128 * PITCH)
#define BH_OFF (256 * PITCH)
#define BL_OFF (BH_OFF + 256 * PITCH)
#define BUF_ELEMS (768 * PITCH)           // 30720 elems
#define BUF_BYTES (BUF_ELEMS * 2)         // 61440 B
#define NSTAGE 3
#define SMEM_BYTES (NSTAGE * BUF_BYTES)   // 184320 B

// ---------------- static device scratch (no allocation allowed) ----------------
__device__ int g_cnt[NEXP], g_curs[NEXP], g_offs[NEXP + 1], g_perm[NTOK];
__device__ __nv_bfloat16 g_Xh[(size_t)NTOK * DDIM], g_Xl[(size_t)NTOK * DDIM];
__device__ __nv_bfloat16 g_W1h[(size_t)HDIM * DDIM], g_W1l[(size_t)HDIM * DDIM];
__device__ __nv_bfloat16 g_W2h[(size_t)DDIM * HDIM], g_W2l[(size_t)DDIM * HDIM];
__device__ __nv_bfloat16 g_Hh[(size_t)NTOK * HDIM], g_Hl[(size_t)NTOK * HDIM];

// ---------------- PTX helpers ----------------
__device__ __forceinline__ void ldm4(unsigned r[4], unsigned addr) {
    asm volatile("ldmatrix.sync.aligned.m8n8.x4.shared.b16 {%0,%1,%2,%3}, [%4];"
                 : "=r"(r[0]), "=r"(r[1]), "=r"(r[2]), "=r"(r[3]) : "r"(addr));
}
__device__ __forceinline__ void mma16816(float d[4], const unsigned a[4], unsigned b0, unsigned b1) {
    asm volatile("mma.sync.aligned.m16n8k16.row.col.f32.bf16.bf16.f32 "
                 "{%0,%1,%2,%3}, {%4,%5,%6,%7}, {%8,%9}, {%0,%1,%2,%3};"
                 : "+f"(d[0]), "+f"(d[1]), "+f"(d[2]), "+f"(d[3])
                 : "r"(a[0]), "r"(a[1]), "r"(a[2]), "r"(a[3]), "r"(b0), "r"(b1));
}
__device__ __forceinline__ void cpa16(unsigned dst, const void* src, bool valid) {
    int sz = valid ? 16 : 0;
    asm volatile("cp.async.cg.shared.global [%0], [%1], 16, %2;" :: "r"(dst), "l"(src), "r"(sz));
}
__device__ __forceinline__ float gelu_exact(float v) {
    return 0.5f * v * (1.0f + erff(v * 0.70710678118654752f));
}

// ---------------- sorting / split / gather kernels ----------------
__global__ void k_init() {
    int i = threadIdx.x;
    if (i < NEXP) { g_cnt[i] = 0; g_curs[i] = 0; }
}
__global__ void k_hist(const int* __restrict__ mask) {
    int t = blockIdx.x * blockDim.x + threadIdx.x;
    if (t < NTOK) atomicAdd(&g_cnt[mask[t]], 1);
}
__global__ void k_prefix() {
    if (threadIdx.x == 0) {
        int s = 0;
        for (int i = 0; i < NEXP; i++) { g_offs[i] = s; s += g_cnt[i]; }
        g_offs[NEXP] = s;
    }
}
__global__ void k_scatter(const int* __restrict__ mask) {
    int t = blockIdx.x * blockDim.x + threadIdx.x;
    if (t < NTOK) {
        int m = mask[t];
        int p = g_offs[m] + atomicAdd(&g_curs[m], 1);
        g_perm[p] = t;
    }
}
__global__ void k_splitW(const float* __restrict__ W, int sel, int n4) {
    int i = blockIdx.x * blockDim.x + threadIdx.x;
    if (i >= n4) return;
    __nv_bfloat16* Wh = sel ? g_W2h : g_W1h;
    __nv_bfloat16* Wl = sel ? g_W2l : g_W1l;
    float4 v = reinterpret_cast<const float4*>(W)[i];
    float vv[4] = {v.x, v.y, v.z, v.w};
    __nv_bfloat16 h[4], l[4];
#pragma unroll
    for (int j = 0; j < 4; j++) {
        h[j] = __float2bfloat16(vv[j]);
        l[j] = __float2bfloat16(vv[j] - __bfloat162float(h[j]));
    }
    reinterpret_cast<__nv_bfloat162*>(Wh)[i * 2 + 0] = __halves2bfloat162(h[0], h[1]);
    reinterpret_cast<__nv_bfloat162*>(Wh)[i * 2 + 1] = __halves2bfloat162(h[2], h[3]);
    reinterpret_cast<__nv_bfloat162*>(Wl)[i * 2 + 0] = __halves2bfloat162(l[0], l[1]);
    reinterpret_cast<__nv_bfloat162*>(Wl)[i * 2 + 1] = __halves2bfloat162(l[2], l[3]);
}
__global__ void k_gather(const float* __restrict__ x) {
    int row = blockIdx.x;
    int src = g_perm[row];
    int t = threadIdx.x;
    float4 v = reinterpret_cast<const float4*>(x + (size_t)src * DDIM)[t];
    float vv[4] = {v.x, v.y, v.z, v.w};
    __nv_bfloat16 h[4], l[4];
#pragma unroll
    for (int j = 0; j < 4; j++) {
        h[j] = __float2bfloat16(vv[j]);
        l[j] = __float2bfloat16(vv[j] - __bfloat162float(h[j]));
    }
    __nv_bfloat162* ph = reinterpret_cast<__nv_bfloat162*>(g_Xh + (size_t)row * DDIM);
    __nv_bfloat162* pl = reinterpret_cast<__nv_bfloat162*>(g_Xl + (size_t)row * DDIM);
    ph[t * 2 + 0] = __halves2bfloat162(h[0], h[1]);
    ph[t * 2 + 1] = __halves2bfloat162(h[2], h[3]);
    pl[t * 2 + 0] = __halves2bfloat162(l[0], l[1]);
    pl[t * 2 + 1] = __halves2bfloat162(l[2], l[3]);
}

// ---------------- tensor-core GEMM (3-term bf16 split, fp32 accum) ----------------
// CTA tile 128(M) x 256(N), K-step 32, 8 warps as 2(M) x 4(N), warp tile 64x64.
// 3-stage cp.async pipeline. S1: epilogue gelu -> Hh/Hl.  !S1: bias -> out[perm].
template <int KM, bool S1>
__global__ __launch_bounds__(256, 1)
void k_mm(const float* __restrict__ bias, float* __restrict__ out, int expert) {
    const int base = g_offs[expert];
    const int cnt  = g_offs[expert + 1] - base;
    const int row0 = blockIdx.x * 128;
    if (row0 >= cnt) return;
    const int col0 = blockIdx.y * 256;

    extern __shared__ __nv_bfloat16 sm[];
    const unsigned sbase = (unsigned)__cvta_generic_to_shared(sm);

    const __nv_bfloat16* Aph = S1 ? g_Xh : g_Hh;
    const __nv_bfloat16* Apl = S1 ? g_Xl : g_Hl;
    const __nv_bfloat16* Bph = S1 ? g_W1h : g_W2h;
    const __nv_bfloat16* Bpl = S1 ? g_W1l : g_W2l;
    const int LD = S1 ? DDIM : HDIM;

    const int tid  = threadIdx.x;
    const int lane = tid & 31;
    const int wrp  = tid >> 5;
    const int wm   = wrp & 1;   // M half: rows wm*64
    const int wn   = wrp >> 1;  // N quarter: cols wn*64

    // ldmatrix lane offsets
    const int a_r  = lane & 15;
    const int a_c8 = (lane >> 4) << 3;
    const int b_n  = (lane & 7) | ((lane >> 4) << 3);
    const int b_k8 = lane & 8;

    float acc[4][8][4];
#pragma unroll
    for (int i = 0; i < 4; i++)
#pragma unroll
        for (int j = 0; j < 8; j++)
#pragma unroll
            for (int q = 0; q < 4; q++) acc[i][j][q] = 0.f;

    auto issue = [&](int buf, int k0) {
        unsigned sb = sbase + buf * BUF_BYTES;
        // A tiles (Ah, Al): 512 x 16B chunks each; chunk c -> row c>>2, pos c&3
#pragma unroll
        for (int t = 0; t < 2; t++) {
#pragma unroll
            for (int j = 0; j < 2; j++) {
                int c = tid + j * 256;
                int row = c >> 2, pos = c & 3;
                bool v = (row0 + row) < cnt;
                int rr = v ? (row0 + row) : 0;
                unsigned dst = sb + (unsigned)((t ? AL_OFF : AH_OFF) + row * PITCH) * 2 + pos * 16;
                const __nv_bfloat16* src = (t ? Apl : Aph) + (size_t)(base + rr) * LD + k0 + pos * 8;
                cpa16(dst, src, v);
            }
        }
        // B tiles (Bh, Bl): 1024 x 16B chunks each
#pragma unroll
        for (int t = 0; t < 2; t++) {
#pragma unroll
            for (int j = 0; j < 4; j++) {
                int c = tid + j * 256;
                int row = c >> 2, pos = c & 3;
                unsigned dst = sb + (unsigned)((t ? BL_OFF : BH_OFF) + row * PITCH) * 2 + pos * 16;
                const __nv_bfloat16* src = (t ? Bpl : Bph) + (size_t)(col0 + row) * LD + k0 + pos * 8;
                cpa16(dst, src, true);
            }
        }
        asm volatile("cp.async.commit_group;");
    };

    const int nK = KM / 32;
    issue(0, 0);
    if (nK > 1) issue(1, 32);

    for (int ki = 0; ki < nK; ki++) {
        if (ki + 2 < nK) {
            issue((ki + 2) % NSTAGE, (ki + 2) * 32);
            asm volatile("cp.async.wait_group 2;");
        } else if (ki + 1 < nK) {
            asm volatile("cp.async.wait_group 1;");
        } else {
            asm volatile("cp.async.wait_group 0;");
        }
        __syncthreads();

        unsigned sb  = sbase + (ki % NSTAGE) * BUF_BYTES;
        unsigned sAh = sb + AH_OFF * 2;
        unsigned sAl = sb + AL_OFF * 2;
        unsigned sBh = sb + BH_OFF * 2;
        unsigned sBl = sb + BL_OFF * 2;

#pragma unroll
        for (int kk = 0; kk < 32; kk += 16) {
            unsigned ah[4][4], al[4][4];
#pragma unroll
            for (int mi = 0; mi < 4; mi++) {
                unsigned off = (unsigned)((wm * 64 + mi * 16 + a_r) * PITCH + kk + a_c8) * 2;
                ldm4(ah[mi], sAh + off);
                ldm4(al[mi], sAl + off);
            }
#pragma unroll
            for (int jp = 0; jp < 4; jp++) {
                unsigned bh[4], bl[4];
                unsigned off = (unsigned)((wn * 64 + jp * 16 + b_n) * PITCH + kk + b_k8) * 2;
                ldm4(bh, sBh + off);
                ldm4(bl, sBl + off);
#pragma unroll
                for (int mi = 0; mi < 4; mi++) {
#pragma unroll
                    for (int s = 0; s < 2; s++) {
                        float* d = acc[mi][jp * 2 + s];
                        mma16816(d, ah[mi], bh[2 * s], bh[2 * s + 1]);   // hi*hi
                        mma16816(d, ah[mi], bl[2 * s], bl[2 * s + 1]);   // hi*lo
                        mma16816(d, al[mi], bh[2 * s], bh[2 * s + 1]);   // lo*hi
                    }
                }
            }
        }
        __syncthreads();
    }

    // ---------------- epilogue ----------------
    const int er = lane >> 2;
    const int ec = (lane & 3) * 2;
#pragma unroll
    for (int mi = 0; mi < 4; mi++) {
#pragma unroll
        for (int nj = 0; nj < 8; nj++) {
            const float* d = acc[mi][nj];
            int c = col0 + wn * 64 + nj * 8 + ec;
            float ba = bias[c], bb = bias[c + 1];
#pragma unroll
            for (int half = 0; half < 2; half++) {
                int r = row0 + wm * 64 + mi * 16 + er + half * 8;
                if (r >= cnt) continue;
                float v0 = d[half * 2 + 0] + ba;
                float v1 = d[half * 2 + 1] + bb;
                if (S1) {
                    v0 = gelu_exact(v0);
                    v1 = gelu_exact(v1);
                    __nv_bfloat16 h0 = __float2bfloat16(v0);
                    __nv_bfloat16 h1 = __float2bfloat16(v1);
                    __nv_bfloat16 l0 = __float2bfloat16(v0 - __bfloat162float(h0));
                    __nv_bfloat16 l1 = __float2bfloat16(v1 - __bfloat162float(h1));
                    size_t o = (size_t)(base + r) * HDIM + c;
                    *reinterpret_cast<__nv_bfloat162*>(g_Hh + o) = __halves2bfloat162(h0, h1);
                    *reinterpret_cast<__nv_bfloat162*>(g_Hl + o) = __halves2bfloat162(l0, l1);
                } else {
                    int tok = g_perm[base + r];
                    float2 o2 = make_float2(v0, v1);
                    *reinterpret_cast<float2*>(out + (size_t)tok * DDIM + c) = o2;
                }
            }
        }
    }
}

// ---------------- launch ----------------
extern "C" void kernel_launch(void* const* d_in, const int* in_sizes, int n_in,
                              void* d_out, int out_size) {
    const float* x    = (const float*)d_in[0];
    const int*   mask = (const int*)d_in[1];
    const float* W1   = (const float*)d_in[2];
    const float* b1   = (const float*)d_in[3];
    const float* W2   = (const float*)d_in[4];
    const float* b2   = (const float*)d_in[5];
    float* out = (float*)d_out;

    cudaFuncSetAttribute(k_mm< 128, true >, cudaFuncAttributeMaxDynamicSharedMemorySize, SMEM_BYTES);
    cudaFuncSetAttribute(k_mm< 256, true >, cudaFuncAttributeMaxDynamicSharedMemorySize, SMEM_BYTES);
    cudaFuncSetAttribute(k_mm< 512, true >, cudaFuncAttributeMaxDynamicSharedMemorySize, SMEM_BYTES);
    cudaFuncSetAttribute(k_mm<1024, true >, cudaFuncAttributeMaxDynamicSharedMemorySize, SMEM_BYTES);
    cudaFuncSetAttribute(k_mm< 512, false>, cudaFuncAttributeMaxDynamicSharedMemorySize, SMEM_BYTES);
    cudaFuncSetAttribute(k_mm<1024, false>, cudaFuncAttributeMaxDynamicSharedMemorySize, SMEM_BYTES);
    cudaFuncSetAttribute(k_mm<2048, false>, cudaFuncAttributeMaxDynamicSharedMemorySize, SMEM_BYTES);
    cudaFuncSetAttribute(k_mm<4096, false>, cudaFuncAttributeMaxDynamicSharedMemorySize, SMEM_BYTES);

    k_init<<<1, 32>>>();
    k_hist<<<NTOK / 256, 256>>>(mask);
    k_prefix<<<1, 32>>>();
    k_scatter<<<NTOK / 256, 256>>>(mask);
    k_splitW<<<(HDIM * DDIM / 4) / 256, 256>>>(W1, 0, HDIM * DDIM / 4);
    k_splitW<<<(DDIM * HDIM / 4) / 256, 256>>>(W2, 1, DDIM * HDIM / 4);
    k_gather<<<NTOK, 256>>>(x);

    // Stage 1: per-expert expand + gelu (row tiles over-launched; device-side early exit)
    k_mm< 128, true ><<<dim3(128,  2), 256, SMEM_BYTES>>>(b1, nullptr, 0);
    k_mm< 256, true ><<<dim3(128,  4), 256, SMEM_BYTES>>>(b1, nullptr, 1);
    k_mm< 512, true ><<<dim3(128,  8), 256, SMEM_BYTES>>>(b1, nullptr, 2);
    k_mm<1024, true ><<<dim3(128, 16), 256, SMEM_BYTES>>>(b1, nullptr, 3);
    // Stage 2: per-expert contract + scatter to original token order
    k_mm< 512, false><<<dim3(128, 4), 256, SMEM_BYTES>>>(b2, out, 0);
    k_mm<1024, false><<<dim3(128, 4), 256, SMEM_BYTES>>>(b2, out, 1);
    k_mm<2048, false><<<dim3(128, 4), 256, SMEM_BYTES>>>(b2, out, 2);
    k_mm<4096, false><<<dim3(128, 4), 256, SMEM_BYTES>>>(b2, out, 3);
}

// round 10
// speedup vs baseline: 2.9921x; 1.3281x over previous
#include <cuda_runtime.h>
#include <cuda_fp16.h>
#include <math.h>
#include <stdint.h>

// Problem constants (fixed shapes for this dataset)
#define NTOK 16384      // B*T
#define DDIM 1024
#define HDIM 4096
#define NEXP 4

#define PITCH 40                  // smem row pitch in fp16 (80B)
// Per-buffer tile layout (elems): A[128*40], Bh[256*40], Bl[256*40]
#define A_OFF  0
#define BH_OFF (128 * PITCH)
#define BL_OFF (384 * PITCH)
#define BUF_ELEMS (640 * PITCH)           // 25600 elems
#define BUF_BYTES (BUF_ELEMS * 2)         // 51200 B
#define NSTAGE 3
#define SMEM_BYTES (NSTAGE * BUF_BYTES)   // 153600 B

// ---------------- static device scratch (no allocation allowed) ----------------
__device__ int g_cnt[NEXP], g_curs[NEXP], g_offs[NEXP + 1], g_perm[NTOK];
__device__ __half g_X16[(size_t)NTOK * DDIM];                       // 32MB
__device__ __half g_W1h[(size_t)HDIM * DDIM], g_W1l[(size_t)HDIM * DDIM];
__device__ __half g_W2h[(size_t)DDIM * HDIM], g_W2l[(size_t)DDIM * HDIM];
__device__ __half g_H16[(size_t)NTOK * HDIM];                       // 128MB

// ---------------- PTX helpers ----------------
__device__ __forceinline__ void ldm4(unsigned r[4], unsigned addr) {
    asm volatile("ldmatrix.sync.aligned.m8n8.x4.shared.b16 {%0,%1,%2,%3}, [%4];"
                 : "=r"(r[0]), "=r"(r[1]), "=r"(r[2]), "=r"(r[3]) : "r"(addr));
}
__device__ __forceinline__ void mma16816(float d[4], const unsigned a[4], unsigned b0, unsigned b1) {
    asm volatile("mma.sync.aligned.m16n8k16.row.col.f32.f16.f16.f32 "
                 "{%0,%1,%2,%3}, {%4,%5,%6,%7}, {%8,%9}, {%0,%1,%2,%3};"
                 : "+f"(d[0]), "+f"(d[1]), "+f"(d[2]), "+f"(d[3])
                 : "r"(a[0]), "r"(a[1]), "r"(a[2]), "r"(a[3]), "r"(b0), "r"(b1));
}
__device__ __forceinline__ void cpa16(unsigned dst, const void* src, bool valid) {
    int sz = valid ? 16 : 0;
    asm volatile("cp.async.cg.shared.global [%0], [%1], 16, %2;" :: "r"(dst), "l"(src), "r"(sz));
}
__device__ __forceinline__ float gelu_exact(float v) {
    return 0.5f * v * (1.0f + erff(v * 0.70710678118654752f));
}

// ---------------- sorting / split / gather kernels ----------------
__global__ void k_init() {
    int i = threadIdx.x;
    if (i < NEXP) { g_cnt[i] = 0; g_curs[i] = 0; }
}
__global__ void k_hist(const int* __restrict__ mask) {
    int t = blockIdx.x * blockDim.x + threadIdx.x;
    if (t < NTOK) atomicAdd(&g_cnt[mask[t]], 1);
}
__global__ void k_prefix() {
    if (threadIdx.x == 0) {
        int s = 0;
        for (int i = 0; i < NEXP; i++) { g_offs[i] = s; s += g_cnt[i]; }
        g_offs[NEXP] = s;
    }
}
__global__ void k_scatter(const int* __restrict__ mask) {
    int t = blockIdx.x * blockDim.x + threadIdx.x;
    if (t < NTOK) {
        int m = mask[t];
        int p = g_offs[m] + atomicAdd(&g_curs[m], 1);
        g_perm[p] = t;
    }
}
// split fp32 weights into fp16 hi + fp16 lo(residual). sel: 0=W1, 1=W2
__global__ void k_splitW(const float* __restrict__ W, int sel, int n4) {
    int i = blockIdx.x * blockDim.x + threadIdx.x;
    if (i >= n4) return;
    __half* Wh = sel ? g_W2h : g_W1h;
    __half* Wl = sel ? g_W2l : g_W1l;
    float4 v = reinterpret_cast<const float4*>(W)[i];
    float vv[4] = {v.x, v.y, v.z, v.w};
    __half h[4], l[4];
#pragma unroll
    for (int j = 0; j < 4; j++) {
        h[j] = __float2half(vv[j]);
        l[j] = __float2half(vv[j] - __half2float(h[j]));
    }
    reinterpret_cast<__half2*>(Wh)[i * 2 + 0] = __halves2half2(h[0], h[1]);
    reinterpret_cast<__half2*>(Wh)[i * 2 + 1] = __halves2half2(h[2], h[3]);
    reinterpret_cast<__half2*>(Wl)[i * 2 + 0] = __halves2half2(l[0], l[1]);
    reinterpret_cast<__half2*>(Wl)[i * 2 + 1] = __halves2half2(l[2], l[3]);
}
// gather sorted rows of x -> fp16. one block per row, 256 thr x float4.
__global__ void k_gather(const float* __restrict__ x) {
    int row = blockIdx.x;
    int src = g_perm[row];
    int t = threadIdx.x;
    float4 v = reinterpret_cast<const float4*>(x + (size_t)src * DDIM)[t];
    __half2* p = reinterpret_cast<__half2*>(g_X16 + (size_t)row * DDIM);
    p[t * 2 + 0] = __halves2half2(__float2half(v.x), __float2half(v.y));
    p[t * 2 + 1] = __halves2half2(__float2half(v.z), __float2half(v.w));
}

// ---------------- tensor-core GEMM (A fp16, B = Wh + Wl fp16 split, fp32 accum) ----------------
// CTA tile 128(M) x 256(N), K-step 32, 8 warps as 2(M) x 4(N), warp tile 64x64.
// 2 MMAs per k16 micro-tile: A*Bh + A*Bl. 3-stage cp.async pipeline.
// S1: epilogue gelu -> g_H16 (fp16).  !S1: bias -> out[perm] fp32.
template <int KM, bool S1>
__global__ __launch_bounds__(256, 1)
void k_mm(const float* __restrict__ bias, float* __restrict__ out, int expert) {
    const int base = g_offs[expert];
    const int cnt  = g_offs[expert + 1] - base;
    const int row0 = blockIdx.x * 128;
    if (row0 >= cnt) return;
    const int col0 = blockIdx.y * 256;

    extern __shared__ __half sm[];
    const unsigned sbase = (unsigned)__cvta_generic_to_shared(sm);

    const __half* Ap  = S1 ? g_X16 : g_H16;
    const __half* Bph = S1 ? g_W1h : g_W2h;
    const __half* Bpl = S1 ? g_W1l : g_W2l;
    const int LD = S1 ? DDIM : HDIM;

    const int tid  = threadIdx.x;
    const int lane = tid & 31;
    const int wrp  = tid >> 5;
    const int wm   = wrp & 1;   // M half: rows wm*64
    const int wn   = wrp >> 1;  // N quarter: cols wn*64

    // ldmatrix lane offsets
    const int a_r  = lane & 15;
    const int a_c8 = (lane >> 4) << 3;
    const int b_n  = (lane & 7) | ((lane >> 4) << 3);
    const int b_k8 = lane & 8;

    float acc[4][8][4];
#pragma unroll
    for (int i = 0; i < 4; i++)
#pragma unroll
        for (int j = 0; j < 8; j++)
#pragma unroll
            for (int q = 0; q < 4; q++) acc[i][j][q] = 0.f;

    auto issue = [&](int buf, int k0) {
        unsigned sb = sbase + buf * BUF_BYTES;
        // A tile: 512 x 16B chunks; chunk c -> row c>>2, pos c&3
#pragma unroll
        for (int j = 0; j < 2; j++) {
            int c = tid + j * 256;
            int row = c >> 2, pos = c & 3;
            bool v = (row0 + row) < cnt;
            int rr = v ? (row0 + row) : 0;
            unsigned dst = sb + (unsigned)(A_OFF + row * PITCH) * 2 + pos * 16;
            const __half* src = Ap + (size_t)(base + rr) * LD + k0 + pos * 8;
            cpa16(dst, src, v);
        }
        // B tiles (Bh, Bl): 1024 x 16B chunks each
#pragma unroll
        for (int t = 0; t < 2; t++) {
#pragma unroll
            for (int j = 0; j < 4; j++) {
                int c = tid + j * 256;
                int row = c >> 2, pos = c & 3;
                unsigned dst = sb + (unsigned)((t ? BL_OFF : BH_OFF) + row * PITCH) * 2 + pos * 16;
                const __half* src = (t ? Bpl : Bph) + (size_t)(col0 + row) * LD + k0 + pos * 8;
                cpa16(dst, src, true);
            }
        }
        asm volatile("cp.async.commit_group;");
    };

    const int nK = KM / 32;
    issue(0, 0);
    if (nK > 1) issue(1, 32);

    for (int ki = 0; ki < nK; ki++) {
        if (ki + 2 < nK) {
            issue((ki + 2) % NSTAGE, (ki + 2) * 32);
            asm volatile("cp.async.wait_group 2;");
        } else if (ki + 1 < nK) {
            asm volatile("cp.async.wait_group 1;");
        } else {
            asm volatile("cp.async.wait_group 0;");
        }
        __syncthreads();

        unsigned sb  = sbase + (ki % NSTAGE) * BUF_BYTES;
        unsigned sA  = sb + A_OFF * 2;
        unsigned sBh = sb + BH_OFF * 2;
        unsigned sBl = sb + BL_OFF * 2;

#pragma unroll
        for (int kk = 0; kk < 32; kk += 16) {
            unsigned ah[4][4];
#pragma unroll
            for (int mi = 0; mi < 4; mi++) {
                unsigned off = (unsigned)((wm * 64 + mi * 16 + a_r) * PITCH + kk + a_c8) * 2;
                ldm4(ah[mi], sA + off);
            }
#pragma unroll
            for (int jp = 0; jp < 4; jp++) {
                unsigned bh[4], bl[4];
                unsigned off = (unsigned)((wn * 64 + jp * 16 + b_n) * PITCH + kk + b_k8) * 2;
                ldm4(bh, sBh + off);
                ldm4(bl, sBl + off);
#pragma unroll
                for (int mi = 0; mi < 4; mi++) {
#pragma unroll
                    for (int s = 0; s < 2; s++) {
                        float* d = acc[mi][jp * 2 + s];
                        mma16816(d, ah[mi], bh[2 * s], bh[2 * s + 1]);   // A * Wh
                        mma16816(d, ah[mi], bl[2 * s], bl[2 * s + 1]);   // A * Wl
                    }
                }
            }
        }
        __syncthreads();
    }

    // ---------------- epilogue ----------------
    const int er = lane >> 2;
    const int ec = (lane & 3) * 2;
#pragma unroll
    for (int mi = 0; mi < 4; mi++) {
#pragma unroll
        for (int nj = 0; nj < 8; nj++) {
            const float* d = acc[mi][nj];
            int c = col0 + wn * 64 + nj * 8 + ec;
            float ba = bias[c], bb = bias[c + 1];
#pragma unroll
            for (int half = 0; half < 2; half++) {
                int r = row0 + wm * 64 + mi * 16 + er + half * 8;
                if (r >= cnt) continue;
                float v0 = d[half * 2 + 0] + ba;
                float v1 = d[half * 2 + 1] + bb;
                if (S1) {
                    v0 = gelu_exact(v0);
                    v1 = gelu_exact(v1);
                    size_t o = (size_t)(base + r) * HDIM + c;
                    *reinterpret_cast<__half2*>(g_H16 + o) =
                        __halves2half2(__float2half(v0), __float2half(v1));
                } else {
                    int tok = g_perm[base + r];
                    float2 o2 = make_float2(v0, v1);
                    *reinterpret_cast<float2*>(out + (size_t)tok * DDIM + c) = o2;
                }
            }
        }
    }
}

// ---------------- launch ----------------
extern "C" void kernel_launch(void* const* d_in, const int* in_sizes, int n_in,
                              void* d_out, int out_size) {
    const float* x    = (const float*)d_in[0];
    const int*   mask = (const int*)d_in[1];
    const float* W1   = (const float*)d_in[2];
    const float* b1   = (const float*)d_in[3];
    const float* W2   = (const float*)d_in[4];
    const float* b2   = (const float*)d_in[5];
    float* out = (float*)d_out;

    cudaFuncSetAttribute(k_mm< 128, true >, cudaFuncAttributeMaxDynamicSharedMemorySize, SMEM_BYTES);
    cudaFuncSetAttribute(k_mm< 256, true >, cudaFuncAttributeMaxDynamicSharedMemorySize, SMEM_BYTES);
    cudaFuncSetAttribute(k_mm< 512, true >, cudaFuncAttributeMaxDynamicSharedMemorySize, SMEM_BYTES);
    cudaFuncSetAttribute(k_mm<1024, true >, cudaFuncAttributeMaxDynamicSharedMemorySize, SMEM_BYTES);
    cudaFuncSetAttribute(k_mm< 512, false>, cudaFuncAttributeMaxDynamicSharedMemorySize, SMEM_BYTES);
    cudaFuncSetAttribute(k_mm<1024, false>, cudaFuncAttributeMaxDynamicSharedMemorySize, SMEM_BYTES);
    cudaFuncSetAttribute(k_mm<2048, false>, cudaFuncAttributeMaxDynamicSharedMemorySize, SMEM_BYTES);
    cudaFuncSetAttribute(k_mm<4096, false>, cudaFuncAttributeMaxDynamicSharedMemorySize, SMEM_BYTES);

    k_init<<<1, 32>>>();
    k_hist<<<NTOK / 256, 256>>>(mask);
    k_prefix<<<1, 32>>>();
    k_scatter<<<NTOK / 256, 256>>>(mask);
    k_splitW<<<(HDIM * DDIM / 4) / 256, 256>>>(W1, 0, HDIM * DDIM / 4);
    k_splitW<<<(DDIM * HDIM / 4) / 256, 256>>>(W2, 1, DDIM * HDIM / 4);
    k_gather<<<NTOK, 256>>>(x);

    // Stage 1: per-expert expand + gelu (row tiles over-launched; device-side early exit)
    k_mm< 128, true ><<<dim3(128,  2), 256, SMEM_BYTES>>>(b1, nullptr, 0);
    k_mm< 256, true ><<<dim3(128,  4), 256, SMEM_BYTES>>>(b1, nullptr, 1);
    k_mm< 512, true ><<<dim3(128,  8), 256, SMEM_BYTES>>>(b1, nullptr, 2);
    k_mm<1024, true ><<<dim3(128, 16), 256, SMEM_BYTES>>>(b1, nullptr, 3);
    // Stage 2: per-expert contract + scatter to original token order
    k_mm< 512, false><<<dim3(128, 4), 256, SMEM_BYTES>>>(b2, out, 0);
    k_mm<1024, false><<<dim3(128, 4), 256, SMEM_BYTES>>>(b2, out, 1);
    k_mm<2048, false><<<dim3(128, 4), 256, SMEM_BYTES>>>(b2, out, 2);
    k_mm<4096, false><<<dim3(128, 4), 256, SMEM_BYTES>>>(b2, out, 3);
}

// round 11
// speedup vs baseline: 4.7512x; 1.5879x over previous
#include <cuda_runtime.h>
#include <cuda_fp16.h>
#include <math.h>
#include <stdint.h>

// Problem constants (fixed shapes for this dataset)
#define NTOK 16384      // B*T
#define DDIM 1024
#define HDIM 4096
#define NEXP 4

#define PITCH 40                  // smem row pitch in fp16 (80B)
// Per-buffer tile layout (elems): A[128*40], B[256*40]
#define A_OFF  0
#define B_OFF  (128 * PITCH)
#define BUF_ELEMS (384 * PITCH)           // 15360 elems
#define BUF_BYTES (BUF_ELEMS * 2)         // 30720 B
#define NSTAGE 4
#define SMEM_BYTES (NSTAGE * BUF_BYTES)   // 122880 B

// ---------------- static device scratch (no allocation allowed) ----------------
__device__ int g_cnt[NEXP], g_curs[NEXP], g_offs[NEXP + 1], g_perm[NTOK];
__device__ __half g_X16[(size_t)NTOK * DDIM];                       // 32MB
__device__ __half g_W1[(size_t)HDIM * DDIM];                        // 8MB
__device__ __half g_W2[(size_t)DDIM * HDIM];                        // 8MB
__device__ __half g_H16[(size_t)NTOK * HDIM];                       // 128MB

// ---------------- PTX helpers ----------------
__device__ __forceinline__ void ldm4(unsigned r[4], unsigned addr) {
    asm volatile("ldmatrix.sync.aligned.m8n8.x4.shared.b16 {%0,%1,%2,%3}, [%4];"
                 : "=r"(r[0]), "=r"(r[1]), "=r"(r[2]), "=r"(r[3]) : "r"(addr));
}
__device__ __forceinline__ void mma16816(float d[4], const unsigned a[4], unsigned b0, unsigned b1) {
    asm volatile("mma.sync.aligned.m16n8k16.row.col.f32.f16.f16.f32 "
                 "{%0,%1,%2,%3}, {%4,%5,%6,%7}, {%8,%9}, {%0,%1,%2,%3};"
                 : "+f"(d[0]), "+f"(d[1]), "+f"(d[2]), "+f"(d[3])
                 : "r"(a[0]), "r"(a[1]), "r"(a[2]), "r"(a[3]), "r"(b0), "r"(b1));
}
__device__ __forceinline__ void cpa16(unsigned dst, const void* src, bool valid) {
    int sz = valid ? 16 : 0;
    asm volatile("cp.async.cg.shared.global [%0], [%1], 16, %2;" :: "r"(dst), "l"(src), "r"(sz));
}
__device__ __forceinline__ float gelu_exact(float v) {
    return 0.5f * v * (1.0f + erff(v * 0.70710678118654752f));
}

// ---------------- sorting / convert / gather kernels ----------------
__global__ void k_init() {
    int i = threadIdx.x;
    if (i < NEXP) { g_cnt[i] = 0; g_curs[i] = 0; }
}
__global__ void k_hist(const int* __restrict__ mask) {
    int t = blockIdx.x * blockDim.x + threadIdx.x;
    if (t < NTOK) atomicAdd(&g_cnt[mask[t]], 1);
}
__global__ void k_prefix() {
    if (threadIdx.x == 0) {
        int s = 0;
        for (int i = 0; i < NEXP; i++) { g_offs[i] = s; s += g_cnt[i]; }
        g_offs[NEXP] = s;
    }
}
__global__ void k_scatter(const int* __restrict__ mask) {
    int t = blockIdx.x * blockDim.x + threadIdx.x;
    if (t < NTOK) {
        int m = mask[t];
        int p = g_offs[m] + atomicAdd(&g_curs[m], 1);
        g_perm[p] = t;
    }
}
// convert fp32 weights -> fp16. sel: 0=W1, 1=W2
__global__ void k_cvtW(const float* __restrict__ W, int sel, int n4) {
    int i = blockIdx.x * blockDim.x + threadIdx.x;
    if (i >= n4) return;
    __half* Wd = sel ? g_W2 : g_W1;
    float4 v = reinterpret_cast<const float4*>(W)[i];
    reinterpret_cast<__half2*>(Wd)[i * 2 + 0] = __halves2half2(__float2half(v.x), __float2half(v.y));
    reinterpret_cast<__half2*>(Wd)[i * 2 + 1] = __halves2half2(__float2half(v.z), __float2half(v.w));
}
// gather sorted rows of x -> fp16. one block per row, 256 thr x float4.
__global__ void k_gather(const float* __restrict__ x) {
    int row = blockIdx.x;
    int src = g_perm[row];
    int t = threadIdx.x;
    float4 v = reinterpret_cast<const float4*>(x + (size_t)src * DDIM)[t];
    __half2* p = reinterpret_cast<__half2*>(g_X16 + (size_t)row * DDIM);
    p[t * 2 + 0] = __halves2half2(__float2half(v.x), __float2half(v.y));
    p[t * 2 + 1] = __halves2half2(__float2half(v.z), __float2half(v.w));
}

// ---------------- tensor-core GEMM (pure fp16, fp32 accum) ----------------
// CTA tile 128(M) x 256(N), K-step 32, 8 warps as 2(M) x 4(N), warp tile 64x64.
// 1 MMA per k16 micro-tile. 4-stage cp.async pipeline.
// S1: epilogue gelu -> g_H16 (fp16).  !S1: bias -> out[perm] fp32.
template <int KM, bool S1>
__global__ __launch_bounds__(256, 1)
void k_mm(const float* __restrict__ bias, float* __restrict__ out, int expert) {
    const int base = g_offs[expert];
    const int cnt  = g_offs[expert + 1] - base;
    const int row0 = blockIdx.x * 128;
    if (row0 >= cnt) return;
    const int col0 = blockIdx.y * 256;

    extern __shared__ __half sm[];
    const unsigned sbase = (unsigned)__cvta_generic_to_shared(sm);

    const __half* Ap = S1 ? g_X16 : g_H16;
    const __half* Bp = S1 ? g_W1  : g_W2;
    const int LD = S1 ? DDIM : HDIM;

    const int tid  = threadIdx.x;
    const int lane = tid & 31;
    const int wrp  = tid >> 5;
    const int wm   = wrp & 1;   // M half: rows wm*64
    const int wn   = wrp >> 1;  // N quarter: cols wn*64

    // ldmatrix lane offsets
    const int a_r  = lane & 15;
    const int a_c8 = (lane >> 4) << 3;
    const int b_n  = (lane & 7) | ((lane >> 4) << 3);
    const int b_k8 = lane & 8;

    float acc[4][8][4];
#pragma unroll
    for (int i = 0; i < 4; i++)
#pragma unroll
        for (int j = 0; j < 8; j++)
#pragma unroll
            for (int q = 0; q < 4; q++) acc[i][j][q] = 0.f;

    auto issue = [&](int buf, int k0) {
        unsigned sb = sbase + buf * BUF_BYTES;
        // A tile: 512 x 16B chunks; chunk c -> row c>>2, pos c&3
#pragma unroll
        for (int j = 0; j < 2; j++) {
            int c = tid + j * 256;
            int row = c >> 2, pos = c & 3;
            bool v = (row0 + row) < cnt;
            int rr = v ? (row0 + row) : 0;
            unsigned dst = sb + (unsigned)(A_OFF + row * PITCH) * 2 + pos * 16;
            const __half* src = Ap + (size_t)(base + rr) * LD + k0 + pos * 8;
            cpa16(dst, src, v);
        }
        // B tile: 1024 x 16B chunks
#pragma unroll
        for (int j = 0; j < 4; j++) {
            int c = tid + j * 256;
            int row = c >> 2, pos = c & 3;
            unsigned dst = sb + (unsigned)(B_OFF + row * PITCH) * 2 + pos * 16;
            const __half* src = Bp + (size_t)(col0 + row) * LD + k0 + pos * 8;
            cpa16(dst, src, true);
        }
        asm volatile("cp.async.commit_group;");
    };

    const int nK = KM / 32;
    issue(0, 0);
    if (nK > 1) issue(1, 32);
    if (nK > 2) issue(2, 64);

    for (int ki = 0; ki < nK; ki++) {
        if (ki + 3 < nK) {
            issue((ki + 3) % NSTAGE, (ki + 3) * 32);
            asm volatile("cp.async.wait_group 3;");
        } else if (ki + 2 < nK) {
            asm volatile("cp.async.wait_group 2;");
        } else if (ki + 1 < nK) {
            asm volatile("cp.async.wait_group 1;");
        } else {
            asm volatile("cp.async.wait_group 0;");
        }
        __syncthreads();

        unsigned sb = sbase + (ki % NSTAGE) * BUF_BYTES;
        unsigned sA = sb + A_OFF * 2;
        unsigned sB = sb + B_OFF * 2;

#pragma unroll
        for (int kk = 0; kk < 32; kk += 16) {
            unsigned ah[4][4];
#pragma unroll
            for (int mi = 0; mi < 4; mi++) {
                unsigned off = (unsigned)((wm * 64 + mi * 16 + a_r) * PITCH + kk + a_c8) * 2;
                ldm4(ah[mi], sA + off);
            }
#pragma unroll
            for (int jp = 0; jp < 4; jp++) {
                unsigned bf[4];
                unsigned off = (unsigned)((wn * 64 + jp * 16 + b_n) * PITCH + kk + b_k8) * 2;
                ldm4(bf, sB + off);
#pragma unroll
                for (int mi = 0; mi < 4; mi++) {
#pragma unroll
                    for (int s = 0; s < 2; s++)
                        mma16816(acc[mi][jp * 2 + s], ah[mi], bf[2 * s], bf[2 * s + 1]);
                }
            }
        }
        __syncthreads();
    }

    // ---------------- epilogue ----------------
    const int er = lane >> 2;
    const int ec = (lane & 3) * 2;
#pragma unroll
    for (int mi = 0; mi < 4; mi++) {
#pragma unroll
        for (int nj = 0; nj < 8; nj++) {
            const float* d = acc[mi][nj];
            int c = col0 + wn * 64 + nj * 8 + ec;
            float ba = bias[c], bb = bias[c + 1];
#pragma unroll
            for (int half = 0; half < 2; half++) {
                int r = row0 + wm * 64 + mi * 16 + er + half * 8;
                if (r >= cnt) continue;
                float v0 = d[half * 2 + 0] + ba;
                float v1 = d[half * 2 + 1] + bb;
                if (S1) {
                    v0 = gelu_exact(v0);
                    v1 = gelu_exact(v1);
                    size_t o = (size_t)(base + r) * HDIM + c;
                    *reinterpret_cast<__half2*>(g_H16 + o) =
                        __halves2half2(__float2half(v0), __float2half(v1));
                } else {
                    int tok = g_perm[base + r];
                    float2 o2 = make_float2(v0, v1);
                    *reinterpret_cast<float2*>(out + (size_t)tok * DDIM + c) = o2;
                }
            }
        }
    }
}

// ---------------- launch ----------------
extern "C" void kernel_launch(void* const* d_in, const int* in_sizes, int n_in,
                              void* d_out, int out_size) {
    const float* x    = (const float*)d_in[0];
    const int*   mask = (const int*)d_in[1];
    const float* W1   = (const float*)d_in[2];
    const float* b1   = (const float*)d_in[3];
    const float* W2   = (const float*)d_in[4];
    const float* b2   = (const float*)d_in[5];
    float* out = (float*)d_out;

    cudaFuncSetAttribute(k_mm< 128, true >, cudaFuncAttributeMaxDynamicSharedMemorySize, SMEM_BYTES);
    cudaFuncSetAttribute(k_mm< 256, true >, cudaFuncAttributeMaxDynamicSharedMemorySize, SMEM_BYTES);
    cudaFuncSetAttribute(k_mm< 512, true >, cudaFuncAttributeMaxDynamicSharedMemorySize, SMEM_BYTES);
    cudaFuncSetAttribute(k_mm<1024, true >, cudaFuncAttributeMaxDynamicSharedMemorySize, SMEM_BYTES);
    cudaFuncSetAttribute(k_mm< 512, false>, cudaFuncAttributeMaxDynamicSharedMemorySize, SMEM_BYTES);
    cudaFuncSetAttribute(k_mm<1024, false>, cudaFuncAttributeMaxDynamicSharedMemorySize, SMEM_BYTES);
    cudaFuncSetAttribute(k_mm<2048, false>, cudaFuncAttributeMaxDynamicSharedMemorySize, SMEM_BYTES);
    cudaFuncSetAttribute(k_mm<4096, false>, cudaFuncAttributeMaxDynamicSharedMemorySize, SMEM_BYTES);

    k_init<<<1, 32>>>();
    k_hist<<<NTOK / 256, 256>>>(mask);
    k_prefix<<<1, 32>>>();
    k_scatter<<<NTOK / 256, 256>>>(mask);
    k_cvtW<<<(HDIM * DDIM / 4) / 256, 256>>>(W1, 0, HDIM * DDIM / 4);
    k_cvtW<<<(DDIM * HDIM / 4) / 256, 256>>>(W2, 1, DDIM * HDIM / 4);
    k_gather<<<NTOK, 256>>>(x);

    // Stage 1: per-expert expand + gelu (row tiles over-launched; device-side early exit)
    k_mm< 128, true ><<<dim3(128,  2), 256, SMEM_BYTES>>>(b1, nullptr, 0);
    k_mm< 256, true ><<<dim3(128,  4), 256, SMEM_BYTES>>>(b1, nullptr, 1);
    k_mm< 512, true ><<<dim3(128,  8), 256, SMEM_BYTES>>>(b1, nullptr, 2);
    k_mm<1024, true ><<<dim3(128, 16), 256, SMEM_BYTES>>>(b1, nullptr, 3);
    // Stage 2: per-expert contract + scatter to original token order
    k_mm< 512, false><<<dim3(128, 4), 256, SMEM_BYTES>>>(b2, out, 0);
    k_mm<1024, false><<<dim3(128, 4), 256, SMEM_BYTES>>>(b2, out, 1);
    k_mm<2048, false><<<dim3(128, 4), 256, SMEM_BYTES>>>(b2, out, 2);
    k_mm<4096, false><<<dim3(128, 4), 256, SMEM_BYTES>>>(b2, out, 3);
}

// round 12
// speedup vs baseline: 5.0161x; 1.0558x over previous
#include <cuda_runtime.h>
#include <cuda_fp16.h>
#include <math.h>
#include <stdint.h>

// Problem constants (fixed shapes for this dataset)
#define NTOK 16384      // B*T
#define DDIM 1024
#define HDIM 4096
#define NEXP 4

#define PITCH 40                  // smem row pitch in fp16 (80B)
// Per-buffer tile layout (elems): A[128*40], B[256*40]
#define A_OFF  0
#define B_OFF  (128 * PITCH)
#define BUF_ELEMS (384 * PITCH)           // 15360 elems
#define BUF_BYTES (BUF_ELEMS * 2)         // 30720 B
#define NSTAGE 4
#define SMEM_BYTES (NSTAGE * BUF_BYTES)   // 122880 B

// ---------------- static device scratch (no allocation allowed) ----------------
__device__ int g_cnt[NEXP], g_curs[NEXP], g_offs[NEXP + 1], g_perm[NTOK];
__device__ __half g_X16[(size_t)NTOK * DDIM];                       // 32MB
__device__ __half g_W1[(size_t)HDIM * DDIM];                        // 8MB
__device__ __half g_W2[(size_t)DDIM * HDIM];                        // 8MB
__device__ __half g_H16[(size_t)NTOK * HDIM];                       // 128MB

// ---------------- PTX helpers ----------------
__device__ __forceinline__ void ldm4(unsigned r[4], unsigned addr) {
    asm volatile("ldmatrix.sync.aligned.m8n8.x4.shared.b16 {%0,%1,%2,%3}, [%4];"
                 : "=r"(r[0]), "=r"(r[1]), "=r"(r[2]), "=r"(r[3]) : "r"(addr));
}
__device__ __forceinline__ void mma16816(float d[4], const unsigned a[4], unsigned b0, unsigned b1) {
    asm volatile("mma.sync.aligned.m16n8k16.row.col.f32.f16.f16.f32 "
                 "{%0,%1,%2,%3}, {%4,%5,%6,%7}, {%8,%9}, {%0,%1,%2,%3};"
                 : "+f"(d[0]), "+f"(d[1]), "+f"(d[2]), "+f"(d[3])
                 : "r"(a[0]), "r"(a[1]), "r"(a[2]), "r"(a[3]), "r"(b0), "r"(b1));
}
__device__ __forceinline__ void cpa16(unsigned dst, const void* src, bool valid) {
    int sz = valid ? 16 : 0;
    asm volatile("cp.async.cg.shared.global [%0], [%1], 16, %2;" :: "r"(dst), "l"(src), "r"(sz));
}
__device__ __forceinline__ float gelu_exact(float v) {
    return 0.5f * v * (1.0f + erff(v * 0.70710678118654752f));
}

// ---------------- sorting / convert / gather kernels ----------------
__global__ void k_init() {
    int i = threadIdx.x;
    if (i < NEXP) { g_cnt[i] = 0; g_curs[i] = 0; }
}
__global__ void k_hist(const int* __restrict__ mask) {
    int t = blockIdx.x * blockDim.x + threadIdx.x;
    if (t < NTOK) atomicAdd(&g_cnt[mask[t]], 1);
}
__global__ void k_prefix() {
    if (threadIdx.x == 0) {
        int s = 0;
        for (int i = 0; i < NEXP; i++) { g_offs[i] = s; s += g_cnt[i]; }
        g_offs[NEXP] = s;
    }
}
__global__ void k_scatter(const int* __restrict__ mask) {
    int t = blockIdx.x * blockDim.x + threadIdx.x;
    if (t < NTOK) {
        int m = mask[t];
        int p = g_offs[m] + atomicAdd(&g_curs[m], 1);
        g_perm[p] = t;
    }
}
// convert both fp32 weight matrices -> fp16 in one launch.
// i in [0, 2M) float4 chunks: first 1M -> W1, second 1M -> W2.
__global__ void k_cvtW(const float* __restrict__ W1, const float* __restrict__ W2) {
    int i = blockIdx.x * blockDim.x + threadIdx.x;
    const int n4 = HDIM * DDIM / 4;
    const float* W = (i < n4) ? W1 : W2;
    __half* Wd = (i < n4) ? g_W1 : g_W2;
    int j = (i < n4) ? i : i - n4;
    float4 v = reinterpret_cast<const float4*>(W)[j];
    reinterpret_cast<__half2*>(Wd)[j * 2 + 0] = __halves2half2(__float2half(v.x), __float2half(v.y));
    reinterpret_cast<__half2*>(Wd)[j * 2 + 1] = __halves2half2(__float2half(v.z), __float2half(v.w));
}
// gather sorted rows of x -> fp16. one block per row, 256 thr x float4.
__global__ void k_gather(const float* __restrict__ x) {
    int row = blockIdx.x;
    int src = g_perm[row];
    int t = threadIdx.x;
    float4 v = reinterpret_cast<const float4*>(x + (size_t)src * DDIM)[t];
    __half2* p = reinterpret_cast<__half2*>(g_X16 + (size_t)row * DDIM);
    p[t * 2 + 0] = __halves2half2(__float2half(v.x), __float2half(v.y));
    p[t * 2 + 1] = __halves2half2(__float2half(v.z), __float2half(v.w));
}

// ---------------- tensor-core GEMM (pure fp16, fp32 accum), ALL experts in one launch ----------------
// CTA tile 128(M) x 256(N), K-step 32, 8 warps as 2(M) x 4(N), warp tile 64x64.
// blockIdx.y encodes (expert, col tile). Runtime KM per expert. 4-stage cp.async pipeline.
// S1: A=X16 (LD=DDIM), B=W1, KM=128<<e, colTiles={2,4,8,16} -> gelu -> g_H16.
// S2: A=H16 (LD=HDIM), B=W2, KM=512<<e, colTiles=4 each -> bias -> out[perm].
template <bool S1>
__global__ __launch_bounds__(256, 1)
void k_mm(const float* __restrict__ bias, float* __restrict__ out) {
    // ---- decode expert / col tile from blockIdx.y ----
    int e, ct;
    if (S1) {
        int y = blockIdx.y;              // 0..29, cumulative colTiles {0,2,6,14,30}
        if (y < 2)       { e = 0; ct = y; }
        else if (y < 6)  { e = 1; ct = y - 2; }
        else if (y < 14) { e = 2; ct = y - 6; }
        else             { e = 3; ct = y - 14; }
    } else {
        e  = blockIdx.y >> 2;            // 0..3
        ct = blockIdx.y & 3;
    }
    const int KM   = (S1 ? 128 : 512) << e;
    const int col0 = ct * 256;

    const int base = g_offs[e];
    const int cnt  = g_offs[e + 1] - base;
    const int row0 = blockIdx.x * 128;
    if (row0 >= cnt) return;

    extern __shared__ __half sm[];
    const unsigned sbase = (unsigned)__cvta_generic_to_shared(sm);

    const __half* Ap = S1 ? g_X16 : g_H16;
    const __half* Bp = S1 ? g_W1  : g_W2;
    const int LD = S1 ? DDIM : HDIM;

    const int tid  = threadIdx.x;
    const int lane = tid & 31;
    const int wrp  = tid >> 5;
    const int wm   = wrp & 1;   // M half: rows wm*64
    const int wn   = wrp >> 1;  // N quarter: cols wn*64

    // ldmatrix lane offsets
    const int a_r  = lane & 15;
    const int a_c8 = (lane >> 4) << 3;
    const int b_n  = (lane & 7) | ((lane >> 4) << 3);
    const int b_k8 = lane & 8;

    float acc[4][8][4];
#pragma unroll
    for (int i = 0; i < 4; i++)
#pragma unroll
        for (int j = 0; j < 8; j++)
#pragma unroll
            for (int q = 0; q < 4; q++) acc[i][j][q] = 0.f;

    auto issue = [&](int buf, int k0) {
        unsigned sb = sbase + buf * BUF_BYTES;
        // A tile: 512 x 16B chunks; chunk c -> row c>>2, pos c&3
#pragma unroll
        for (int j = 0; j < 2; j++) {
            int c = tid + j * 256;
            int row = c >> 2, pos = c & 3;
            bool v = (row0 + row) < cnt;
            int rr = v ? (row0 + row) : 0;
            unsigned dst = sb + (unsigned)(A_OFF + row * PITCH) * 2 + pos * 16;
            const __half* src = Ap + (size_t)(base + rr) * LD + k0 + pos * 8;
            cpa16(dst, src, v);
        }
        // B tile: 1024 x 16B chunks
#pragma unroll
        for (int j = 0; j < 4; j++) {
            int c = tid + j * 256;
            int row = c >> 2, pos = c & 3;
            unsigned dst = sb + (unsigned)(B_OFF + row * PITCH) * 2 + pos * 16;
            const __half* src = Bp + (size_t)(col0 + row) * LD + k0 + pos * 8;
            cpa16(dst, src, true);
        }
        asm volatile("cp.async.commit_group;");
    };

    const int nK = KM / 32;
    issue(0, 0);
    if (nK > 1) issue(1, 32);
    if (nK > 2) issue(2, 64);

    for (int ki = 0; ki < nK; ki++) {
        if (ki + 3 < nK) {
            issue((ki + 3) % NSTAGE, (ki + 3) * 32);
            asm volatile("cp.async.wait_group 3;");
        } else if (ki + 2 < nK) {
            asm volatile("cp.async.wait_group 2;");
        } else if (ki + 1 < nK) {
            asm volatile("cp.async.wait_group 1;");
        } else {
            asm volatile("cp.async.wait_group 0;");
        }
        __syncthreads();

        unsigned sb = sbase + (ki % NSTAGE) * BUF_BYTES;
        unsigned sA = sb + A_OFF * 2;
        unsigned sB = sb + B_OFF * 2;

#pragma unroll
        for (int kk = 0; kk < 32; kk += 16) {
            unsigned ah[4][4];
#pragma unroll
            for (int mi = 0; mi < 4; mi++) {
                unsigned off = (unsigned)((wm * 64 + mi * 16 + a_r) * PITCH + kk + a_c8) * 2;
                ldm4(ah[mi], sA + off);
            }
#pragma unroll
            for (int jp = 0; jp < 4; jp++) {
                unsigned bf[4];
                unsigned off = (unsigned)((wn * 64 + jp * 16 + b_n) * PITCH + kk + b_k8) * 2;
                ldm4(bf, sB + off);
#pragma unroll
                for (int mi = 0; mi < 4; mi++) {
#pragma unroll
                    for (int s = 0; s < 2; s++)
                        mma16816(acc[mi][jp * 2 + s], ah[mi], bf[2 * s], bf[2 * s + 1]);
                }
            }
        }
        __syncthreads();
    }

    // ---------------- epilogue ----------------
    const int er = lane >> 2;
    const int ec = (lane & 3) * 2;
#pragma unroll
    for (int mi = 0; mi < 4; mi++) {
#pragma unroll
        for (int nj = 0; nj < 8; nj++) {
            const float* d = acc[mi][nj];
            int c = col0 + wn * 64 + nj * 8 + ec;
            float ba = bias[c], bb = bias[c + 1];
#pragma unroll
            for (int half = 0; half < 2; half++) {
                int r = row0 + wm * 64 + mi * 16 + er + half * 8;
                if (r >= cnt) continue;
                float v0 = d[half * 2 + 0] + ba;
                float v1 = d[half * 2 + 1] + bb;
                if (S1) {
                    v0 = gelu_exact(v0);
                    v1 = gelu_exact(v1);
                    size_t o = (size_t)(base + r) * HDIM + c;
                    *reinterpret_cast<__half2*>(g_H16 + o) =
                        __halves2half2(__float2half(v0), __float2half(v1));
                } else {
                    int tok = g_perm[base + r];
                    float2 o2 = make_float2(v0, v1);
                    *reinterpret_cast<float2*>(out + (size_t)tok * DDIM + c) = o2;
                }
            }
        }
    }
}

// ---------------- launch ----------------
extern "C" void kernel_launch(void* const* d_in, const int* in_sizes, int n_in,
                              void* d_out, int out_size) {
    const float* x    = (const float*)d_in[0];
    const int*   mask = (const int*)d_in[1];
    const float* W1   = (const float*)d_in[2];
    const float* b1   = (const float*)d_in[3];
    const float* W2   = (const float*)d_in[4];
    const float* b2   = (const float*)d_in[5];
    float* out = (float*)d_out;

    cudaFuncSetAttribute(k_mm<true >, cudaFuncAttributeMaxDynamicSharedMemorySize, SMEM_BYTES);
    cudaFuncSetAttribute(k_mm<false>, cudaFuncAttributeMaxDynamicSharedMemorySize, SMEM_BYTES);

    k_init<<<1, 32>>>();
    k_hist<<<NTOK / 256, 256>>>(mask);
    k_prefix<<<1, 32>>>();
    k_scatter<<<NTOK / 256, 256>>>(mask);
    k_cvtW<<<(2 * HDIM * DDIM / 4) / 256, 256>>>(W1, W2);
    k_gather<<<NTOK, 256>>>(x);

    // Stage 1: ALL experts in one launch. y: 30 (expert,colTile) pairs; x: row tiles (early exit).
    k_mm<true ><<<dim3(128, 30), 256, SMEM_BYTES>>>(b1, nullptr);
    // Stage 2: ALL experts in one launch. y: 16 pairs (4 experts x 4 col tiles).
    k_mm<false><<<dim3(128, 16), 256, SMEM_BYTES>>>(b2, out);
}

// round 13
// speedup vs baseline: 6.4683x; 1.2895x over previous
#include <cuda_runtime.h>
#include <cuda_fp16.h>
#include <math.h>
#include <stdint.h>

// Problem constants (fixed shapes for this dataset)
#define NTOK 16384      // B*T
#define DDIM 1024
#define HDIM 4096
#define NEXP 4

#define PITCH 40                  // smem row pitch in fp16 (80B)
// Per-buffer tile layout (elems): A[128*40], B[128*40]
#define A_OFF  0
#define B_OFF  (128 * PITCH)
#define BUF_ELEMS (256 * PITCH)           // 10240 elems
#define BUF_BYTES (BUF_ELEMS * 2)         // 20480 B
#define NSTAGE 3
#define SMEM_BYTES (NSTAGE * BUF_BYTES)   // 61440 B -> 2 CTAs/SM

// ---------------- static device scratch (no allocation allowed) ----------------
__device__ int g_cnt[NEXP], g_curs[NEXP], g_offs[NEXP + 1], g_perm[NTOK];
__device__ __half g_X16[(size_t)NTOK * DDIM];                       // 32MB
__device__ __half g_W1[(size_t)HDIM * DDIM];                        // 8MB
__device__ __half g_W2[(size_t)DDIM * HDIM];                        // 8MB
__device__ __half g_H16[(size_t)NTOK * HDIM];                       // 128MB

// ---------------- PTX helpers ----------------
__device__ __forceinline__ void ldm4(unsigned r[4], unsigned addr) {
    asm volatile("ldmatrix.sync.aligned.m8n8.x4.shared.b16 {%0,%1,%2,%3}, [%4];"
                 : "=r"(r[0]), "=r"(r[1]), "=r"(r[2]), "=r"(r[3]) : "r"(addr));
}
__device__ __forceinline__ void mma16816(float d[4], const unsigned a[4], unsigned b0, unsigned b1) {
    asm volatile("mma.sync.aligned.m16n8k16.row.col.f32.f16.f16.f32 "
                 "{%0,%1,%2,%3}, {%4,%5,%6,%7}, {%8,%9}, {%0,%1,%2,%3};"
                 : "+f"(d[0]), "+f"(d[1]), "+f"(d[2]), "+f"(d[3])
                 : "r"(a[0]), "r"(a[1]), "r"(a[2]), "r"(a[3]), "r"(b0), "r"(b1));
}
__device__ __forceinline__ void cpa16(unsigned dst, const void* src, bool valid) {
    int sz = valid ? 16 : 0;
    asm volatile("cp.async.cg.shared.global [%0], [%1], 16, %2;" :: "r"(dst), "l"(src), "r"(sz));
}
__device__ __forceinline__ float gelu_exact(float v) {
    return 0.5f * v * (1.0f + erff(v * 0.70710678118654752f));
}

// ---------------- sorting / convert / gather kernels ----------------
__global__ void k_init() {
    int i = threadIdx.x;
    if (i < NEXP) { g_cnt[i] = 0; g_curs[i] = 0; }
}
__global__ void k_hist(const int* __restrict__ mask) {
    int t = blockIdx.x * blockDim.x + threadIdx.x;
    if (t < NTOK) atomicAdd(&g_cnt[mask[t]], 1);
}
__global__ void k_prefix() {
    if (threadIdx.x == 0) {
        int s = 0;
        for (int i = 0; i < NEXP; i++) { g_offs[i] = s; s += g_cnt[i]; }
        g_offs[NEXP] = s;
    }
}
__global__ void k_scatter(const int* __restrict__ mask) {
    int t = blockIdx.x * blockDim.x + threadIdx.x;
    if (t < NTOK) {
        int m = mask[t];
        int p = g_offs[m] + atomicAdd(&g_curs[m], 1);
        g_perm[p] = t;
    }
}
// convert both fp32 weight matrices -> fp16 in one launch.
__global__ void k_cvtW(const float* __restrict__ W1, const float* __restrict__ W2) {
    int i = blockIdx.x * blockDim.x + threadIdx.x;
    const int n4 = HDIM * DDIM / 4;
    const float* W = (i < n4) ? W1 : W2;
    __half* Wd = (i < n4) ? g_W1 : g_W2;
    int j = (i < n4) ? i : i - n4;
    float4 v = reinterpret_cast<const float4*>(W)[j];
    reinterpret_cast<__half2*>(Wd)[j * 2 + 0] = __halves2half2(__float2half(v.x), __float2half(v.y));
    reinterpret_cast<__half2*>(Wd)[j * 2 + 1] = __halves2half2(__float2half(v.z), __float2half(v.w));
}
// gather sorted rows of x -> fp16. one block per row, 256 thr x float4.
__global__ void k_gather(const float* __restrict__ x) {
    int row = blockIdx.x;
    int src = g_perm[row];
    int t = threadIdx.x;
    float4 v = reinterpret_cast<const float4*>(x + (size_t)src * DDIM)[t];
    __half2* p = reinterpret_cast<__half2*>(g_X16 + (size_t)row * DDIM);
    p[t * 2 + 0] = __halves2half2(__float2half(v.x), __float2half(v.y));
    p[t * 2 + 1] = __halves2half2(__float2half(v.z), __float2half(v.w));
}

// ---------------- tensor-core GEMM (pure fp16, fp32 accum), ALL experts in one launch ----------------
// CTA tile 128(M) x 128(N), K-step 32, 8 warps as 4(M) x 2(N), warp tile 32x64.
// 3-stage cp.async pipeline, 2 CTAs/SM. Longest-K experts scheduled FIRST (reversed y decode).
// S1: A=X16 (LD=DDIM), B=W1, KM=128<<e, colTiles(128)={4,8,16,32} -> gelu -> g_H16.
// S2: A=H16 (LD=HDIM), B=W2, KM=512<<e, colTiles=8 each -> bias -> out[perm].
template <bool S1>
__global__ __launch_bounds__(256, 2)
void k_mm(const float* __restrict__ bias, float* __restrict__ out) {
    // ---- decode expert / col tile from blockIdx.y (heavy experts first) ----
    int e, ct;
    if (S1) {
        int y = blockIdx.y;              // 0..59: e=3 first (32 tiles), then 16, 8, 4
        if (y < 32)      { e = 3; ct = y; }
        else if (y < 48) { e = 2; ct = y - 32; }
        else if (y < 56) { e = 1; ct = y - 48; }
        else             { e = 0; ct = y - 56; }
    } else {
        e  = 3 - (blockIdx.y >> 3);      // 0..31: e=3 first
        ct = blockIdx.y & 7;
    }
    const int KM   = (S1 ? 128 : 512) << e;
    const int col0 = ct * 128;

    const int base = g_offs[e];
    const int cnt  = g_offs[e + 1] - base;
    const int row0 = blockIdx.x * 128;
    if (row0 >= cnt) return;

    extern __shared__ __half sm[];
    const unsigned sbase = (unsigned)__cvta_generic_to_shared(sm);

    const __half* Ap = S1 ? g_X16 : g_H16;
    const __half* Bp = S1 ? g_W1  : g_W2;
    const int LD = S1 ? DDIM : HDIM;

    const int tid  = threadIdx.x;
    const int lane = tid & 31;
    const int wrp  = tid >> 5;
    const int wm   = wrp & 3;   // M quad: rows wm*32
    const int wn   = wrp >> 2;  // N half: cols wn*64

    // ldmatrix lane offsets
    const int a_r  = lane & 15;
    const int a_c8 = (lane >> 4) << 3;
    const int b_n  = (lane & 7) | ((lane >> 4) << 3);
    const int b_k8 = lane & 8;

    float acc[2][8][4];
#pragma unroll
    for (int i = 0; i < 2; i++)
#pragma unroll
        for (int j = 0; j < 8; j++)
#pragma unroll
            for (int q = 0; q < 4; q++) acc[i][j][q] = 0.f;

    auto issue = [&](int buf, int k0) {
        unsigned sb = sbase + buf * BUF_BYTES;
        // A tile: 512 x 16B chunks; chunk c -> row c>>2, pos c&3
#pragma unroll
        for (int j = 0; j < 2; j++) {
            int c = tid + j * 256;
            int row = c >> 2, pos = c & 3;
            bool v = (row0 + row) < cnt;
            int rr = v ? (row0 + row) : 0;
            unsigned dst = sb + (unsigned)(A_OFF + row * PITCH) * 2 + pos * 16;
            const __half* src = Ap + (size_t)(base + rr) * LD + k0 + pos * 8;
            cpa16(dst, src, v);
        }
        // B tile: 512 x 16B chunks
#pragma unroll
        for (int j = 0; j < 2; j++) {
            int c = tid + j * 256;
            int row = c >> 2, pos = c & 3;
            unsigned dst = sb + (unsigned)(B_OFF + row * PITCH) * 2 + pos * 16;
            const __half* src = Bp + (size_t)(col0 + row) * LD + k0 + pos * 8;
            cpa16(dst, src, true);
        }
        asm volatile("cp.async.commit_group;");
    };

    const int nK = KM / 32;
    issue(0, 0);
    if (nK > 1) issue(1, 32);

    for (int ki = 0; ki < nK; ki++) {
        if (ki + 2 < nK) {
            issue((ki + 2) % NSTAGE, (ki + 2) * 32);
            asm volatile("cp.async.wait_group 2;");
        } else if (ki + 1 < nK) {
            asm volatile("cp.async.wait_group 1;");
        } else {
            asm volatile("cp.async.wait_group 0;");
        }
        __syncthreads();

        unsigned sb = sbase + (ki % NSTAGE) * BUF_BYTES;
        unsigned sA = sb + A_OFF * 2;
        unsigned sB = sb + B_OFF * 2;

#pragma unroll
        for (int kk = 0; kk < 32; kk += 16) {
            unsigned ah[2][4];
#pragma unroll
            for (int mi = 0; mi < 2; mi++) {
                unsigned off = (unsigned)((wm * 32 + mi * 16 + a_r) * PITCH + kk + a_c8) * 2;
                ldm4(ah[mi], sA + off);
            }
#pragma unroll
            for (int jp = 0; jp < 4; jp++) {
                unsigned bf[4];
                unsigned off = (unsigned)((wn * 64 + jp * 16 + b_n) * PITCH + kk + b_k8) * 2;
                ldm4(bf, sB + off);
#pragma unroll
                for (int mi = 0; mi < 2; mi++) {
#pragma unroll
                    for (int s = 0; s < 2; s++)
                        mma16816(acc[mi][jp * 2 + s], ah[mi], bf[2 * s], bf[2 * s + 1]);
                }
            }
        }
        __syncthreads();
    }

    // ---------------- epilogue ----------------
    const int er = lane >> 2;
    const int ec = (lane & 3) * 2;
#pragma unroll
    for (int mi = 0; mi < 2; mi++) {
#pragma unroll
        for (int nj = 0; nj < 8; nj++) {
            const float* d = acc[mi][nj];
            int c = col0 + wn * 64 + nj * 8 + ec;
            float ba = bias[c], bb = bias[c + 1];
#pragma unroll
            for (int half = 0; half < 2; half++) {
                int r = row0 + wm * 32 + mi * 16 + er + half * 8;
                if (r >= cnt) continue;
                float v0 = d[half * 2 + 0] + ba;
                float v1 = d[half * 2 + 1] + bb;
                if (S1) {
                    v0 = gelu_exact(v0);
                    v1 = gelu_exact(v1);
                    size_t o = (size_t)(base + r) * HDIM + c;
                    *reinterpret_cast<__half2*>(g_H16 + o) =
                        __halves2half2(__float2half(v0), __float2half(v1));
                } else {
                    int tok = g_perm[base + r];
                    float2 o2 = make_float2(v0, v1);
                    *reinterpret_cast<float2*>(out + (size_t)tok * DDIM + c) = o2;
                }
            }
        }
    }
}

// ---------------- launch ----------------
extern "C" void kernel_launch(void* const* d_in, const int* in_sizes, int n_in,
                              void* d_out, int out_size) {
    const float* x    = (const float*)d_in[0];
    const int*   mask = (const int*)d_in[1];
    const float* W1   = (const float*)d_in[2];
    const float* b1   = (const float*)d_in[3];
    const float* W2   = (const float*)d_in[4];
    const float* b2   = (const float*)d_in[5];
    float* out = (float*)d_out;

    cudaFuncSetAttribute(k_mm<true >, cudaFuncAttributeMaxDynamicSharedMemorySize, SMEM_BYTES);
    cudaFuncSetAttribute(k_mm<false>, cudaFuncAttributeMaxDynamicSharedMemorySize, SMEM_BYTES);

    k_init<<<1, 32>>>();
    k_hist<<<NTOK / 256, 256>>>(mask);
    k_prefix<<<1, 32>>>();
    k_scatter<<<NTOK / 256, 256>>>(mask);
    k_cvtW<<<(2 * HDIM * DDIM / 4) / 256, 256>>>(W1, W2);
    k_gather<<<NTOK, 256>>>(x);

    // Stage 1: ALL experts, one launch. y: 60 (expert,colTile) pairs, heavy experts first.
    k_mm<true ><<<dim3(128, 60), 256, SMEM_BYTES>>>(b1, nullptr);
    // Stage 2: ALL experts, one launch. y: 32 pairs (4 experts x 8 col tiles), heavy first.
    k_mm<false><<<dim3(128, 32), 256, SMEM_BYTES>>>(b2, out);
}